// round 3
// baseline (speedup 1.0000x reference)
#include <cuda_runtime.h>
#include <math.h>
#include <stdint.h>

#define BATCH 4
#define CC 256
#define CI 128
#define NPIX 2304
#define BNEPS 1e-5f
#define NCHUNK 18
#define ETSPLIT 18   // 2304/18 = 128 per split

// ---------------- scratch ----------------
__device__ float g_PRE[4][BATCH][CI*NPIX];
__device__ float g_ETpart[BATCH][ETSPLIT][CI*CI];
__device__ float g_ET[BATCH][CI*CI];
__device__ float g_A1[BATCH][CI*CI];
__device__ float g_A2[BATCH][CI*CI];
__device__ float g_E[BATCH][NPIX*NPIX];
__device__ float g_Z[2][BATCH][CI*NPIX];
__device__ float g_Y[2][BATCH][CI*NPIX];
__device__ float g_colmax[BATCH][NPIX];
__device__ float g_colrsum[BATCH][NPIX];
__device__ float g_rowmax[BATCH][NPIX];
__device__ float g_rowrsum[BATCH][NPIX];
__device__ float g_pmax[BATCH][NCHUNK][NPIX];
__device__ float g_psum[BATCH][NCHUNK][NPIX];
__device__ float g_WpreH[4][CI*CC];
__device__ float g_WpreL[4][CI*CC];
__device__ float g_bpre[4][CI];
__device__ float g_Wpost[2][CC*CI];
__device__ float g_bpost[2][CC];

// ---------------- tf32 helpers ----------------
__device__ __forceinline__ uint32_t f2t(float x) {
    uint32_t r;
    asm("cvt.rna.tf32.f32 %0, %1;" : "=r"(r) : "f"(x));
    return r;
}
__device__ __forceinline__ void f2t_split(float x, uint32_t& hi, uint32_t& lo) {
    hi = f2t(x);
    lo = f2t(x - __uint_as_float(hi));
}
__device__ __forceinline__ void mma8(float c[4], const uint32_t a[4], const uint32_t b[2]) {
    asm volatile(
        "mma.sync.aligned.m16n8k8.row.col.f32.tf32.tf32.f32 "
        "{%0,%1,%2,%3}, {%4,%5,%6,%7}, {%8,%9}, {%0,%1,%2,%3};"
        : "+f"(c[0]), "+f"(c[1]), "+f"(c[2]), "+f"(c[3])
        : "r"(a[0]), "r"(a[1]), "r"(a[2]), "r"(a[3]), "r"(b[0]), "r"(b[1]));
}

// ---------------- BN folding (+ W hi/lo pre-split) ----------------
__global__ void k_fold(const float* __restrict__ bn_pre, const float* __restrict__ w_pre,
                       const float* __restrict__ b_pre, const float* __restrict__ w_post,
                       const float* __restrict__ b_post, const float* __restrict__ bn_post)
{
    int tid = threadIdx.x;
    if (blockIdx.x == 0) {
        int i = tid >> 7, o = tid & 127;
        const float* bp = bn_pre + i * 4 * CC;
        const float* w  = w_pre + (i * CI + o) * CC;
        float acc = b_pre[i * CI + o];
        for (int c = 0; c < CC; c++) {
            float s = bp[c] * rsqrtf(bp[3 * CC + c] + BNEPS);
            float t = bp[CC + c] - bp[2 * CC + c] * s;
            float wv = w[c] * s;
            uint32_t h = f2t(wv);
            g_WpreH[i][o * CC + c] = __uint_as_float(h);
            g_WpreL[i][o * CC + c] = __uint_as_float(f2t(wv - __uint_as_float(h)));
            acc += w[c] * t;
        }
        g_bpre[i][o] = acc;
    } else {
        int i = tid >> 8, o = tid & 255;
        const float* bp = bn_post + i * 4 * CC;
        float s = bp[o] * rsqrtf(bp[3 * CC + o] + BNEPS);
        const float* w = w_post + (i * CC + o) * CI;
        for (int c = 0; c < CI; c++)
            g_Wpost[i][o * CI + c] = w[c] * s;
        g_bpost[i][o] = b_post[i * CC + o] * s + bp[CC + o] - bp[2 * CC + o] * s;
    }
}

// ======================================================================
// k_pre_mma: PRE[i][b] = Wpre[i](3-term tf32) @ x + bpre
// M=128, K=256, N=2304.  Block tile 128x128, 16 warps, K-chunk 16.
// A layout [m][k] (stride 20), B layout [k][n] (stride 136), hi/lo pairs.
// ======================================================================
__global__ void __launch_bounds__(512) k_pre_mma(const float* __restrict__ x1,
                                                 const float* __restrict__ x2)
{
    int i = blockIdx.z >> 2, b = blockIdx.z & 3;
    int n0 = blockIdx.x * 128;
    const float* __restrict__ AH = g_WpreH[i];
    const float* __restrict__ AL = g_WpreL[i];
    const float* __restrict__ Bsrc = ((i & 1) ? x2 : x1) + b * CC * NPIX;

    __shared__ uint32_t Ah[128][20], Al[128][20];
    __shared__ uint32_t Bh[16][136], Bl[16][136];

    int tid = threadIdx.x;
    int wid = tid >> 5, lane = tid & 31;
    int g = lane >> 2, tig = lane & 3;
    int wm = (wid & 3) * 32, wn = (wid >> 2) * 32;

    float c[2][4][4] = {};

    for (int k0 = 0; k0 < CC; k0 += 16) {
        {   // A chunk 128x16
            int m = tid >> 2, kq = (tid & 3) * 4;
            float4 h4 = *(const float4*)&AH[m * CC + k0 + kq];
            float4 l4 = *(const float4*)&AL[m * CC + k0 + kq];
            Ah[m][kq+0]=__float_as_uint(h4.x); Ah[m][kq+1]=__float_as_uint(h4.y);
            Ah[m][kq+2]=__float_as_uint(h4.z); Ah[m][kq+3]=__float_as_uint(h4.w);
            Al[m][kq+0]=__float_as_uint(l4.x); Al[m][kq+1]=__float_as_uint(l4.y);
            Al[m][kq+2]=__float_as_uint(l4.z); Al[m][kq+3]=__float_as_uint(l4.w);
        }
        {   // B chunk 16x128, split on the fly
            int kk = tid >> 5, jq = (tid & 31) * 4;
            float4 b4 = *(const float4*)&Bsrc[(k0 + kk) * NPIX + n0 + jq];
            uint32_t h0,l0,h1,l1,h2,l2,h3,l3;
            f2t_split(b4.x,h0,l0); f2t_split(b4.y,h1,l1);
            f2t_split(b4.z,h2,l2); f2t_split(b4.w,h3,l3);
            Bh[kk][jq+0]=h0; Bh[kk][jq+1]=h1; Bh[kk][jq+2]=h2; Bh[kk][jq+3]=h3;
            Bl[kk][jq+0]=l0; Bl[kk][jq+1]=l1; Bl[kk][jq+2]=l2; Bl[kk][jq+3]=l3;
        }
        __syncthreads();
#pragma unroll
        for (int kk = 0; kk < 16; kk += 8) {
            uint32_t ah[2][4], al[2][4];
#pragma unroll
            for (int mi = 0; mi < 2; mi++) {
                int mr = wm + mi * 16;
                ah[mi][0]=Ah[mr+g  ][kk+tig  ]; ah[mi][1]=Ah[mr+g+8][kk+tig  ];
                ah[mi][2]=Ah[mr+g  ][kk+tig+4]; ah[mi][3]=Ah[mr+g+8][kk+tig+4];
                al[mi][0]=Al[mr+g  ][kk+tig  ]; al[mi][1]=Al[mr+g+8][kk+tig  ];
                al[mi][2]=Al[mr+g  ][kk+tig+4]; al[mi][3]=Al[mr+g+8][kk+tig+4];
            }
#pragma unroll
            for (int ni = 0; ni < 4; ni++) {
                uint32_t bh[2], bl[2];
                bh[0]=Bh[kk+tig  ][wn+ni*8+g]; bh[1]=Bh[kk+tig+4][wn+ni*8+g];
                bl[0]=Bl[kk+tig  ][wn+ni*8+g]; bl[1]=Bl[kk+tig+4][wn+ni*8+g];
#pragma unroll
                for (int mi = 0; mi < 2; mi++) {
                    mma8(c[mi][ni], ah[mi], bh);
                    mma8(c[mi][ni], ah[mi], bl);
                    mma8(c[mi][ni], al[mi], bh);
                }
            }
        }
        __syncthreads();
    }

    float* Cout = g_PRE[i][b];
#pragma unroll
    for (int mi = 0; mi < 2; mi++) {
#pragma unroll
        for (int ni = 0; ni < 4; ni++) {
            int row = wm + mi * 16 + g;
            int col = n0 + wn + ni * 8 + tig * 2;
            float b0 = g_bpre[i][row], b1 = g_bpre[i][row + 8];
            *(float2*)&Cout[row * NPIX + col] =
                make_float2(c[mi][ni][0] + b0, c[mi][ni][1] + b0);
            *(float2*)&Cout[(row + 8) * NPIX + col] =
                make_float2(c[mi][ni][2] + b1, c[mi][ni][3] + b1);
        }
    }
}

// ======================================================================
// k_etime_mma: ETpart[b][ks] = T @ P^T over K-slice, 3-term tf32.
// M=N=128 (one tile), K-slice = 128, chunk 16. B layout [n][k].
// ======================================================================
__global__ void __launch_bounds__(512) k_etime_mma()
{
    int b = blockIdx.x / ETSPLIT, ks = blockIdx.x % ETSPLIT;
    int kbeg = ks * (NPIX / ETSPLIT);
    const float* __restrict__ T = g_PRE[2][b];
    const float* __restrict__ P = g_PRE[3][b];

    __shared__ uint32_t Ah[128][20], Al[128][20];
    __shared__ uint32_t Bh[128][20], Bl[128][20];

    int tid = threadIdx.x;
    int wid = tid >> 5, lane = tid & 31;
    int g = lane >> 2, tig = lane & 3;
    int wm = (wid & 3) * 32, wn = (wid >> 2) * 32;

    float c[2][4][4] = {};

    for (int k0 = kbeg; k0 < kbeg + NPIX / ETSPLIT; k0 += 16) {
        int m = tid >> 2, kq = (tid & 3) * 4;
        float4 t4 = *(const float4*)&T[m * NPIX + k0 + kq];
        float4 p4 = *(const float4*)&P[m * NPIX + k0 + kq];
        uint32_t h0,l0,h1,l1,h2,l2,h3,l3;
        f2t_split(t4.x,h0,l0); f2t_split(t4.y,h1,l1);
        f2t_split(t4.z,h2,l2); f2t_split(t4.w,h3,l3);
        Ah[m][kq+0]=h0; Ah[m][kq+1]=h1; Ah[m][kq+2]=h2; Ah[m][kq+3]=h3;
        Al[m][kq+0]=l0; Al[m][kq+1]=l1; Al[m][kq+2]=l2; Al[m][kq+3]=l3;
        f2t_split(p4.x,h0,l0); f2t_split(p4.y,h1,l1);
        f2t_split(p4.z,h2,l2); f2t_split(p4.w,h3,l3);
        Bh[m][kq+0]=h0; Bh[m][kq+1]=h1; Bh[m][kq+2]=h2; Bh[m][kq+3]=h3;
        Bl[m][kq+0]=l0; Bl[m][kq+1]=l1; Bl[m][kq+2]=l2; Bl[m][kq+3]=l3;
        __syncthreads();
#pragma unroll
        for (int kk = 0; kk < 16; kk += 8) {
            uint32_t ah[2][4], al[2][4];
#pragma unroll
            for (int mi = 0; mi < 2; mi++) {
                int mr = wm + mi * 16;
                ah[mi][0]=Ah[mr+g  ][kk+tig  ]; ah[mi][1]=Ah[mr+g+8][kk+tig  ];
                ah[mi][2]=Ah[mr+g  ][kk+tig+4]; ah[mi][3]=Ah[mr+g+8][kk+tig+4];
                al[mi][0]=Al[mr+g  ][kk+tig  ]; al[mi][1]=Al[mr+g+8][kk+tig  ];
                al[mi][2]=Al[mr+g  ][kk+tig+4]; al[mi][3]=Al[mr+g+8][kk+tig+4];
            }
#pragma unroll
            for (int ni = 0; ni < 4; ni++) {
                int nr = wn + ni * 8 + g;
                uint32_t bh[2], bl[2];
                bh[0]=Bh[nr][kk+tig]; bh[1]=Bh[nr][kk+tig+4];
                bl[0]=Bl[nr][kk+tig]; bl[1]=Bl[nr][kk+tig+4];
#pragma unroll
                for (int mi = 0; mi < 2; mi++) {
                    mma8(c[mi][ni], ah[mi], bh);
                    mma8(c[mi][ni], ah[mi], bl);
                    mma8(c[mi][ni], al[mi], bh);
                }
            }
        }
        __syncthreads();
    }

    float* outp = g_ETpart[b][ks];
#pragma unroll
    for (int mi = 0; mi < 2; mi++) {
#pragma unroll
        for (int ni = 0; ni < 4; ni++) {
            int row = wm + mi * 16 + g;
            int col = wn + ni * 8 + tig * 2;
            *(float2*)&outp[row * CI + col]       = make_float2(c[mi][ni][0], c[mi][ni][1]);
            *(float2*)&outp[(row + 8) * CI + col] = make_float2(c[mi][ni][2], c[mi][ni][3]);
        }
    }
}

__global__ void k_etreduce()
{
    int b = blockIdx.y, idx = blockIdx.x * 256 + threadIdx.x;
    float s = 0.f;
#pragma unroll
    for (int p = 0; p < ETSPLIT; p++) s += g_ETpart[b][p][idx];
    g_ET[b][idx] = s;
}

__global__ void k_softmax_time()
{
    int b = blockIdx.x, t = threadIdx.x;
    const float* ET = g_ET[b];
    float mx = -3.0e38f;
    for (int d = 0; d < CI; d++) mx = fmaxf(mx, ET[t * CI + d]);
    float s = 0.f;
    for (int d = 0; d < CI; d++) s += __expf(ET[t * CI + d] - mx);
    float rs = 1.f / s;
    for (int d = 0; d < CI; d++) g_A2[b][t * CI + d] = __expf(ET[t * CI + d] - mx) * rs;
    mx = -3.0e38f;
    for (int d = 0; d < CI; d++) mx = fmaxf(mx, ET[d * CI + t]);
    s = 0.f;
    for (int d = 0; d < CI; d++) s += __expf(ET[d * CI + t] - mx);
    rs = 1.f / s;
    for (int d = 0; d < CI; d++) g_A1[b][t * CI + d] = __expf(ET[d * CI + t] - mx) * rs;
}

// ======================================================================
// k_zgemm_mma: Z = A @ G  (single-pass tf32). M=128, K=128, N=2304.
// Block 128x128, chunk 32. A [m][k] stride 36; B [k][n] stride 136.
// ======================================================================
__global__ void __launch_bounds__(512) k_zgemm_mma()
{
    int zi = blockIdx.z >> 2, b = blockIdx.z & 3;
    int n0 = blockIdx.x * 128;
    const float* __restrict__ Asrc = zi ? g_A2[b] : g_A1[b];
    const float* __restrict__ Bsrc = g_PRE[zi][b];

    __shared__ uint32_t As[128][36];
    __shared__ uint32_t Bs[32][136];

    int tid = threadIdx.x;
    int wid = tid >> 5, lane = tid & 31;
    int g = lane >> 2, tig = lane & 3;
    int wm = (wid & 3) * 32, wn = (wid >> 2) * 32;

    float c[2][4][4] = {};

    for (int k0 = 0; k0 < CI; k0 += 32) {
#pragma unroll
        for (int it = 0; it < 2; it++) {
            int v = tid + it * 512;
            int m = v >> 3, kq = (v & 7) * 4;
            float4 a4 = *(const float4*)&Asrc[m * CI + k0 + kq];
            As[m][kq+0]=f2t(a4.x); As[m][kq+1]=f2t(a4.y);
            As[m][kq+2]=f2t(a4.z); As[m][kq+3]=f2t(a4.w);
        }
#pragma unroll
        for (int it = 0; it < 2; it++) {
            int v = tid + it * 512;
            int kk = v >> 5, jq = (v & 31) * 4;
            float4 b4 = *(const float4*)&Bsrc[(k0 + kk) * NPIX + n0 + jq];
            Bs[kk][jq+0]=f2t(b4.x); Bs[kk][jq+1]=f2t(b4.y);
            Bs[kk][jq+2]=f2t(b4.z); Bs[kk][jq+3]=f2t(b4.w);
        }
        __syncthreads();
#pragma unroll
        for (int kk = 0; kk < 32; kk += 8) {
            uint32_t a[2][4];
#pragma unroll
            for (int mi = 0; mi < 2; mi++) {
                int mr = wm + mi * 16;
                a[mi][0]=As[mr+g  ][kk+tig  ]; a[mi][1]=As[mr+g+8][kk+tig  ];
                a[mi][2]=As[mr+g  ][kk+tig+4]; a[mi][3]=As[mr+g+8][kk+tig+4];
            }
#pragma unroll
            for (int ni = 0; ni < 4; ni++) {
                uint32_t bb[2];
                bb[0]=Bs[kk+tig  ][wn+ni*8+g];
                bb[1]=Bs[kk+tig+4][wn+ni*8+g];
                mma8(c[0][ni], a[0], bb);
                mma8(c[1][ni], a[1], bb);
            }
        }
        __syncthreads();
    }

    float* Zout = g_Z[zi][b];
#pragma unroll
    for (int mi = 0; mi < 2; mi++) {
#pragma unroll
        for (int ni = 0; ni < 4; ni++) {
            int row = wm + mi * 16 + g;
            int col = n0 + wn + ni * 8 + tig * 2;
            *(float2*)&Zout[row * NPIX + col]       = make_float2(c[mi][ni][0], c[mi][ni][1]);
            *(float2*)&Zout[(row + 8) * NPIX + col] = make_float2(c[mi][ni][2], c[mi][ni][3]);
        }
    }
}

// ======================================================================
// e_space via 3-term tf32 (unchanged from R2)
// ======================================================================
__global__ void __launch_bounds__(256) k_espace_mma()
{
    int b = blockIdx.z;
    int row0 = blockIdx.y * 128, col0 = blockIdx.x * 64;
    const float* __restrict__ T = g_PRE[2][b];
    const float* __restrict__ P = g_PRE[3][b];

    __shared__ uint32_t Ah[32][136], Al[32][136];
    __shared__ uint32_t Bh[32][72],  Bl[32][72];

    int tid = threadIdx.x;
    int wid = tid >> 5, lane = tid & 31;
    int g = lane >> 2, tig = lane & 3;
    int wm = (wid & 3) * 32, wn = (wid >> 2) * 32;

    float c[2][4][4] = {};

    for (int k0 = 0; k0 < CI; k0 += 32) {
#pragma unroll
        for (int it = 0; it < 4; it++) {
            int v = tid + it * 256;
            int r = v >> 5, c4 = (v & 31) * 4;
            float4 t4 = *(const float4*)&T[(k0 + r) * NPIX + row0 + c4];
            uint32_t h0,l0,h1,l1,h2,l2,h3,l3;
            f2t_split(t4.x, h0, l0); f2t_split(t4.y, h1, l1);
            f2t_split(t4.z, h2, l2); f2t_split(t4.w, h3, l3);
            Ah[r][c4+0]=h0; Ah[r][c4+1]=h1; Ah[r][c4+2]=h2; Ah[r][c4+3]=h3;
            Al[r][c4+0]=l0; Al[r][c4+1]=l1; Al[r][c4+2]=l2; Al[r][c4+3]=l3;
        }
#pragma unroll
        for (int it = 0; it < 2; it++) {
            int v = tid + it * 256;
            int r = v >> 4, c4 = (v & 15) * 4;
            float4 p4 = *(const float4*)&P[(k0 + r) * NPIX + col0 + c4];
            uint32_t h0,l0,h1,l1,h2,l2,h3,l3;
            f2t_split(p4.x, h0, l0); f2t_split(p4.y, h1, l1);
            f2t_split(p4.z, h2, l2); f2t_split(p4.w, h3, l3);
            Bh[r][c4+0]=h0; Bh[r][c4+1]=h1; Bh[r][c4+2]=h2; Bh[r][c4+3]=h3;
            Bl[r][c4+0]=l0; Bl[r][c4+1]=l1; Bl[r][c4+2]=l2; Bl[r][c4+3]=l3;
        }
        __syncthreads();
#pragma unroll
        for (int kk = 0; kk < 32; kk += 8) {
            uint32_t ah[2][4], al[2][4];
#pragma unroll
            for (int mi = 0; mi < 2; mi++) {
                int mr = wm + mi * 16;
                ah[mi][0] = Ah[kk+tig  ][mr + g    ];
                ah[mi][1] = Ah[kk+tig  ][mr + g + 8];
                ah[mi][2] = Ah[kk+tig+4][mr + g    ];
                ah[mi][3] = Ah[kk+tig+4][mr + g + 8];
                al[mi][0] = Al[kk+tig  ][mr + g    ];
                al[mi][1] = Al[kk+tig  ][mr + g + 8];
                al[mi][2] = Al[kk+tig+4][mr + g    ];
                al[mi][3] = Al[kk+tig+4][mr + g + 8];
            }
#pragma unroll
            for (int ni = 0; ni < 4; ni++) {
                uint32_t bh[2], bl[2];
                bh[0] = Bh[kk+tig  ][wn + ni*8 + g];
                bh[1] = Bh[kk+tig+4][wn + ni*8 + g];
                bl[0] = Bl[kk+tig  ][wn + ni*8 + g];
                bl[1] = Bl[kk+tig+4][wn + ni*8 + g];
#pragma unroll
                for (int mi = 0; mi < 2; mi++) {
                    mma8(c[mi][ni], ah[mi], bh);
                    mma8(c[mi][ni], ah[mi], bl);
                    mma8(c[mi][ni], al[mi], bh);
                }
            }
        }
        __syncthreads();
    }

    float* Ep = g_E[b];
#pragma unroll
    for (int mi = 0; mi < 2; mi++) {
#pragma unroll
        for (int ni = 0; ni < 4; ni++) {
            int row = row0 + wm + mi * 16 + g;
            int col = col0 + wn + ni * 8 + tig * 2;
            *(float2*)&Ep[row * NPIX + col]       = make_float2(c[mi][ni][0], c[mi][ni][1]);
            *(float2*)&Ep[(row + 8) * NPIX + col] = make_float2(c[mi][ni][2], c[mi][ni][3]);
        }
    }
}

// ---------------- e_space stats (unchanged) ----------------
__global__ void k_colpart()
{
    int b = blockIdx.z, ch = blockIdx.y;
    int m = blockIdx.x * 256 + threadIdx.x;
    const float* Ep = g_E[b];
    float mx = -3.0e38f, s = 0.f;
    int n0 = ch * (NPIX / NCHUNK);
    for (int n = n0; n < n0 + NPIX / NCHUNK; n++) {
        float v = Ep[n * NPIX + m];
        if (v > mx) { s = s * __expf(mx - v) + 1.f; mx = v; }
        else        { s += __expf(v - mx); }
    }
    g_pmax[b][ch][m] = mx;
    g_psum[b][ch][m] = s;
}

__global__ void k_colreduce()
{
    int b = blockIdx.y, m = blockIdx.x * 256 + threadIdx.x;
    float mx = -3.0e38f, s = 0.f;
#pragma unroll
    for (int ch = 0; ch < NCHUNK; ch++) {
        float pm = g_pmax[b][ch][m], ps = g_psum[b][ch][m];
        float nm = fmaxf(mx, pm);
        s = s * __expf(mx - nm) + ps * __expf(pm - nm);
        mx = nm;
    }
    g_colmax[b][m] = mx;
    g_colrsum[b][m] = 1.f / s;
}

__global__ void k_rowstats()
{
    int b = blockIdx.y;
    int n = blockIdx.x * 8 + (threadIdx.x >> 5);
    int lane = threadIdx.x & 31;
    const float* row = g_E[b] + n * NPIX;
    float mx = -3.0e38f, s = 0.f;
    for (int m = lane; m < NPIX; m += 32) {
        float v = row[m];
        if (v > mx) { s = s * __expf(mx - v) + 1.f; mx = v; }
        else        { s += __expf(v - mx); }
    }
#pragma unroll
    for (int off = 16; off; off >>= 1) {
        float om = __shfl_xor_sync(0xffffffffu, mx, off);
        float os = __shfl_xor_sync(0xffffffffu, s, off);
        float nm = fmaxf(mx, om);
        s = s * __expf(mx - nm) + os * __expf(om - nm);
        mx = nm;
    }
    if (lane == 0) { g_rowmax[b][n] = mx; g_rowrsum[b][n] = 1.f / s; }
}

// ======================================================================
// Y GEMMs with fused softmax B-load (unchanged from R2)
// ======================================================================
__global__ void __launch_bounds__(512) k_ygemm_mma()
{
    int yi = blockIdx.z >> 2, b = blockIdx.z & 3;
    int n0 = blockIdx.x * 128;
    const float* __restrict__ Zp = g_Z[yi][b];
    const float* __restrict__ Ep = g_E[b];
    const float* __restrict__ vmax = yi ? g_rowmax[b]  : g_colmax[b];
    const float* __restrict__ vrs  = yi ? g_rowrsum[b] : g_colrsum[b];

    __shared__ uint32_t As[128][36];
    __shared__ uint32_t BsRaw[128 * 36];
    __shared__ float s_max[128], s_rs[128];

    int tid = threadIdx.x;
    if (tid < 128) { s_max[tid] = vmax[n0 + tid]; s_rs[tid] = vrs[n0 + tid]; }
    __syncthreads();

    int wid = tid >> 5, lane = tid & 31;
    int g = lane >> 2, tig = lane & 3;
    int wm = (wid & 3) * 32, wn = (wid >> 2) * 32;

    float c[2][4][4] = {};

    for (int k0 = 0; k0 < NPIX; k0 += 32) {
#pragma unroll
        for (int it = 0; it < 2; it++) {
            int v = tid + it * 512;
            int m = v >> 3, kq = (v & 7) * 4;
            float4 z4 = *(const float4*)&Zp[m * NPIX + k0 + kq];
            As[m][kq+0] = f2t(z4.x); As[m][kq+1] = f2t(z4.y);
            As[m][kq+2] = f2t(z4.z); As[m][kq+3] = f2t(z4.w);
        }
        if (yi == 0) {
#pragma unroll
            for (int it = 0; it < 2; it++) {
                int v = tid + it * 512;
                int kk = v >> 5, jq = (v & 31) * 4;
                float4 e4 = *(const float4*)&Ep[(k0 + kk) * NPIX + n0 + jq];
                uint32_t* brow = &BsRaw[kk * 136];
                brow[jq+0] = f2t(__expf(e4.x - s_max[jq+0]));
                brow[jq+1] = f2t(__expf(e4.y - s_max[jq+1]));
                brow[jq+2] = f2t(__expf(e4.z - s_max[jq+2]));
                brow[jq+3] = f2t(__expf(e4.w - s_max[jq+3]));
            }
        } else {
#pragma unroll
            for (int it = 0; it < 2; it++) {
                int v = tid + it * 512;
                int j = v >> 3, kq = (v & 7) * 4;
                float4 e4 = *(const float4*)&Ep[(n0 + j) * NPIX + k0 + kq];
                float mxj = s_max[j];
                uint32_t* brow = &BsRaw[j * 36];
                brow[kq+0] = f2t(__expf(e4.x - mxj));
                brow[kq+1] = f2t(__expf(e4.y - mxj));
                brow[kq+2] = f2t(__expf(e4.z - mxj));
                brow[kq+3] = f2t(__expf(e4.w - mxj));
            }
        }
        __syncthreads();
#pragma unroll
        for (int kk = 0; kk < 32; kk += 8) {
            uint32_t a[2][4];
#pragma unroll
            for (int mi = 0; mi < 2; mi++) {
                int mr = wm + mi * 16;
                a[mi][0] = As[mr + g    ][kk + tig    ];
                a[mi][1] = As[mr + g + 8][kk + tig    ];
                a[mi][2] = As[mr + g    ][kk + tig + 4];
                a[mi][3] = As[mr + g + 8][kk + tig + 4];
            }
#pragma unroll
            for (int ni = 0; ni < 4; ni++) {
                uint32_t bb[2];
                if (yi == 0) {
                    bb[0] = BsRaw[(kk + tig    ) * 136 + wn + ni*8 + g];
                    bb[1] = BsRaw[(kk + tig + 4) * 136 + wn + ni*8 + g];
                } else {
                    bb[0] = BsRaw[(wn + ni*8 + g) * 36 + kk + tig    ];
                    bb[1] = BsRaw[(wn + ni*8 + g) * 36 + kk + tig + 4];
                }
                mma8(c[0][ni], a[0], bb);
                mma8(c[1][ni], a[1], bb);
            }
        }
        __syncthreads();
    }

    float* Yp = g_Y[yi][b];
#pragma unroll
    for (int mi = 0; mi < 2; mi++) {
#pragma unroll
        for (int ni = 0; ni < 4; ni++) {
            int row = wm + mi * 16 + g;
            int col = wn + ni * 8 + tig * 2;
            float r0 = s_rs[col], r1 = s_rs[col + 1];
            *(float2*)&Yp[row * NPIX + n0 + col] =
                make_float2(c[mi][ni][0] * r0, c[mi][ni][1] * r1);
            *(float2*)&Yp[(row + 8) * NPIX + n0 + col] =
                make_float2(c[mi][ni][2] * r0, c[mi][ni][3] * r1);
        }
    }
}

// ======================================================================
// k_post_mma: out = Wpost @ Y + bias + residual. M=256, K=128, N=2304.
// Single-pass tf32. Block 128x128, grid.y = 2 M-tiles.
// ======================================================================
__global__ void __launch_bounds__(512) k_post_mma(const float* __restrict__ x1,
                                                  const float* __restrict__ x2,
                                                  float* __restrict__ out)
{
    int i = blockIdx.z >> 2, b = blockIdx.z & 3;
    int m0 = blockIdx.y * 128, n0 = blockIdx.x * 128;
    const float* __restrict__ Asrc = g_Wpost[i];
    const float* __restrict__ Bsrc = g_Y[i][b];

    __shared__ uint32_t As[128][36];
    __shared__ uint32_t Bs[32][136];

    int tid = threadIdx.x;
    int wid = tid >> 5, lane = tid & 31;
    int g = lane >> 2, tig = lane & 3;
    int wm = (wid & 3) * 32, wn = (wid >> 2) * 32;

    float c[2][4][4] = {};

    for (int k0 = 0; k0 < CI; k0 += 32) {
#pragma unroll
        for (int it = 0; it < 2; it++) {
            int v = tid + it * 512;
            int m = v >> 3, kq = (v & 7) * 4;
            float4 a4 = *(const float4*)&Asrc[(m0 + m) * CI + k0 + kq];
            As[m][kq+0]=f2t(a4.x); As[m][kq+1]=f2t(a4.y);
            As[m][kq+2]=f2t(a4.z); As[m][kq+3]=f2t(a4.w);
        }
#pragma unroll
        for (int it = 0; it < 2; it++) {
            int v = tid + it * 512;
            int kk = v >> 5, jq = (v & 31) * 4;
            float4 b4 = *(const float4*)&Bsrc[(k0 + kk) * NPIX + n0 + jq];
            Bs[kk][jq+0]=f2t(b4.x); Bs[kk][jq+1]=f2t(b4.y);
            Bs[kk][jq+2]=f2t(b4.z); Bs[kk][jq+3]=f2t(b4.w);
        }
        __syncthreads();
#pragma unroll
        for (int kk = 0; kk < 32; kk += 8) {
            uint32_t a[2][4];
#pragma unroll
            for (int mi = 0; mi < 2; mi++) {
                int mr = wm + mi * 16;
                a[mi][0]=As[mr+g  ][kk+tig  ]; a[mi][1]=As[mr+g+8][kk+tig  ];
                a[mi][2]=As[mr+g  ][kk+tig+4]; a[mi][3]=As[mr+g+8][kk+tig+4];
            }
#pragma unroll
            for (int ni = 0; ni < 4; ni++) {
                uint32_t bb[2];
                bb[0]=Bs[kk+tig  ][wn+ni*8+g];
                bb[1]=Bs[kk+tig+4][wn+ni*8+g];
                mma8(c[0][ni], a[0], bb);
                mma8(c[1][ni], a[1], bb);
            }
        }
        __syncthreads();
    }

    const float* xs = (i ? x2 : x1) + b * CC * NPIX;
    float* op = out + (size_t)i * BATCH * CC * NPIX + (size_t)b * CC * NPIX;
#pragma unroll
    for (int mi = 0; mi < 2; mi++) {
#pragma unroll
        for (int ni = 0; ni < 4; ni++) {
            int row = m0 + wm + mi * 16 + g;
            int col = n0 + wn + ni * 8 + tig * 2;
            float b0 = g_bpost[i][row], b1 = g_bpost[i][row + 8];
            float2 r0 = *(const float2*)&xs[row * NPIX + col];
            float2 r1 = *(const float2*)&xs[(row + 8) * NPIX + col];
            *(float2*)&op[row * NPIX + col] =
                make_float2(c[mi][ni][0] + b0 + r0.x, c[mi][ni][1] + b0 + r0.y);
            *(float2*)&op[(row + 8) * NPIX + col] =
                make_float2(c[mi][ni][2] + b1 + r1.x, c[mi][ni][3] + b1 + r1.y);
        }
    }
}

// ---------------- launcher ----------------
extern "C" void kernel_launch(void* const* d_in, const int* in_sizes, int n_in,
                              void* d_out, int out_size)
{
    const float* x1      = (const float*)d_in[0];
    const float* x2      = (const float*)d_in[1];
    const float* bn_pre  = (const float*)d_in[2];
    const float* w_pre   = (const float*)d_in[3];
    const float* b_pre   = (const float*)d_in[4];
    const float* w_post  = (const float*)d_in[5];
    const float* b_post  = (const float*)d_in[6];
    const float* bn_post = (const float*)d_in[7];
    float* out = (float*)d_out;

    k_fold<<<2, 512>>>(bn_pre, w_pre, b_pre, w_post, b_post, bn_post);
    k_pre_mma<<<dim3(18, 1, 16), 512>>>(x1, x2);
    k_etime_mma<<<BATCH * ETSPLIT, 512>>>();
    k_etreduce<<<dim3(64, BATCH), 256>>>();
    k_softmax_time<<<BATCH, 128>>>();
    k_espace_mma<<<dim3(36, 18, BATCH), 256>>>();
    k_zgemm_mma<<<dim3(18, 1, 8), 512>>>();
    k_colpart<<<dim3(9, NCHUNK, BATCH), 256>>>();
    k_colreduce<<<dim3(9, BATCH), 256>>>();
    k_rowstats<<<dim3(288, BATCH), 256>>>();
    k_ygemm_mma<<<dim3(18, 1, 8), 512>>>();
    k_post_mma<<<dim3(18, 2, 8), 512>>>(x1, x2, out);
}

// round 4
// speedup vs baseline: 1.0763x; 1.0763x over previous
#include <cuda_runtime.h>
#include <cuda_bf16.h>
#include <math.h>
#include <stdint.h>

#define BATCH 4
#define CC 256
#define CI 128
#define NPIX 2304
#define BNEPS 1e-5f
#define NCHUNK 18
#define ETSPLIT 18

// ---------------- scratch ----------------
__device__ float g_PRE[4][BATCH][CI*NPIX];
__device__ float g_ETpart[BATCH][ETSPLIT][CI*CI];
__device__ float g_ET[BATCH][CI*CI];
__device__ float g_A1[BATCH][CI*CI];
__device__ float g_A2[BATCH][CI*CI];
__device__ float g_E[BATCH][NPIX*NPIX];
__device__ float g_Z[2][BATCH][CI*NPIX];
__device__ float g_Y[2][BATCH][CI*NPIX];
__device__ float g_colmax[BATCH][NPIX];
__device__ float g_colrsum[BATCH][NPIX];
__device__ float g_rowmax[BATCH][NPIX];
__device__ float g_rowrsum[BATCH][NPIX];
__device__ float g_pmax[BATCH][NCHUNK][NPIX];
__device__ float g_psum[BATCH][NCHUNK][NPIX];
__device__ float g_WpreH[4][CI*CC];
__device__ float g_WpreL[4][CI*CC];
__device__ float g_bpre[4][CI];
__device__ float g_Wpost[2][CC*CI];
__device__ float g_bpost[2][CC];

// ---------------- tf32 helpers ----------------
__device__ __forceinline__ uint32_t f2t(float x) {
    uint32_t r;
    asm("cvt.rna.tf32.f32 %0, %1;" : "=r"(r) : "f"(x));
    return r;
}
__device__ __forceinline__ void f2t_split(float x, uint32_t& hi, uint32_t& lo) {
    hi = f2t(x);
    lo = f2t(x - __uint_as_float(hi));
}
__device__ __forceinline__ void mma8(float c[4], const uint32_t a[4], const uint32_t b[2]) {
    asm volatile(
        "mma.sync.aligned.m16n8k8.row.col.f32.tf32.tf32.f32 "
        "{%0,%1,%2,%3}, {%4,%5,%6,%7}, {%8,%9}, {%0,%1,%2,%3};"
        : "+f"(c[0]), "+f"(c[1]), "+f"(c[2]), "+f"(c[3])
        : "r"(a[0]), "r"(a[1]), "r"(a[2]), "r"(a[3]), "r"(b[0]), "r"(b[1]));
}

// ---------------- bf16 helpers ----------------
// pack(e, o): low half = e (even-k element), high half = o (odd-k element)
__device__ __forceinline__ uint32_t pack_bf(float e, float o) {
    uint32_t r;
    asm("cvt.rn.bf16x2.f32 %0, %1, %2;" : "=r"(r) : "f"(o), "f"(e));
    return r;
}
__device__ __forceinline__ float bf_round(float x) {
    return __bfloat162float(__float2bfloat16(x));
}
__device__ __forceinline__ void mma16bf(float c[4], const uint32_t a[4], const uint32_t b[2]) {
    asm volatile(
        "mma.sync.aligned.m16n8k16.row.col.f32.bf16.bf16.f32 "
        "{%0,%1,%2,%3}, {%4,%5,%6,%7}, {%8,%9}, {%0,%1,%2,%3};"
        : "+f"(c[0]), "+f"(c[1]), "+f"(c[2]), "+f"(c[3])
        : "r"(a[0]), "r"(a[1]), "r"(a[2]), "r"(a[3]), "r"(b[0]), "r"(b[1]));
}
// split two floats (even,odd k) into hi-packed and lo-packed bf16x2
__device__ __forceinline__ void split_pack(float e, float o, uint32_t& hp, uint32_t& lp) {
    float eh = bf_round(e), oh = bf_round(o);
    hp = pack_bf(eh, oh);
    lp = pack_bf(e - eh, o - oh);
}

// ---------------- BN folding ----------------
__global__ void k_fold(const float* __restrict__ bn_pre, const float* __restrict__ w_pre,
                       const float* __restrict__ b_pre, const float* __restrict__ w_post,
                       const float* __restrict__ b_post, const float* __restrict__ bn_post)
{
    int tid = threadIdx.x;
    if (blockIdx.x == 0) {
        int i = tid >> 7, o = tid & 127;
        const float* bp = bn_pre + i * 4 * CC;
        const float* w  = w_pre + (i * CI + o) * CC;
        float acc = b_pre[i * CI + o];
        for (int c = 0; c < CC; c++) {
            float s = bp[c] * rsqrtf(bp[3 * CC + c] + BNEPS);
            float t = bp[CC + c] - bp[2 * CC + c] * s;
            float wv = w[c] * s;
            float h = bf_round(wv);
            g_WpreH[i][o * CC + c] = h;
            g_WpreL[i][o * CC + c] = wv - h;
            acc += w[c] * t;
        }
        g_bpre[i][o] = acc;
    } else {
        int i = tid >> 8, o = tid & 255;
        const float* bp = bn_post + i * 4 * CC;
        float s = bp[o] * rsqrtf(bp[3 * CC + o] + BNEPS);
        const float* w = w_post + (i * CC + o) * CI;
        for (int c = 0; c < CI; c++)
            g_Wpost[i][o * CI + c] = w[c] * s;
        g_bpost[i][o] = b_post[i * CC + o] * s + bp[CC + o] - bp[2 * CC + o] * s;
    }
}

// ======================================================================
// k_pre_bf16: PRE[i][b] = Wpre[i] @ x + bpre   (3-term bf16 m16n8k16)
// M=128, K=256, N=2304. Block tile 128x64, 8 warps (4x2), K-chunk 32.
// A packed [m][k2] stride 20 (hi/lo); B packed [k2][n] stride 72 (hi/lo).
// ======================================================================
__global__ void __launch_bounds__(256) k_pre_bf16(const float* __restrict__ x1,
                                                  const float* __restrict__ x2)
{
    int i = blockIdx.z >> 2, b = blockIdx.z & 3;
    int n0 = blockIdx.x * 64;
    const float* __restrict__ AHf = g_WpreH[i];
    const float* __restrict__ ALf = g_WpreL[i];
    const float* __restrict__ Bsrc = ((i & 1) ? x2 : x1) + b * CC * NPIX;

    __shared__ uint32_t Ah[128][20], Al[128][20];
    __shared__ uint32_t Bh[16][72],  Bl[16][72];

    int tid = threadIdx.x;
    int wid = tid >> 5, lane = tid & 31;
    int g = lane >> 2, tig = lane & 3;
    int wm = (wid & 3) * 32, wn = (wid >> 2) * 32;

    float c[2][4][4] = {};

    for (int k0 = 0; k0 < CC; k0 += 32) {
        // A: W hi/lo already split; just pack pairs. 128x16 packed entries.
#pragma unroll
        for (int it = 0; it < 2; it++) {
            int v = tid + it * 256;
            int m = v >> 2, kq = (v & 3) * 8;
            float4 h0 = *(const float4*)&AHf[m * CC + k0 + kq];
            float4 h1 = *(const float4*)&AHf[m * CC + k0 + kq + 4];
            float4 l0 = *(const float4*)&ALf[m * CC + k0 + kq];
            float4 l1 = *(const float4*)&ALf[m * CC + k0 + kq + 4];
            *(uint4*)&Ah[m][kq >> 1] = make_uint4(
                pack_bf(h0.x, h0.y), pack_bf(h0.z, h0.w),
                pack_bf(h1.x, h1.y), pack_bf(h1.z, h1.w));
            *(uint4*)&Al[m][kq >> 1] = make_uint4(
                pack_bf(l0.x, l0.y), pack_bf(l0.z, l0.w),
                pack_bf(l1.x, l1.y), pack_bf(l1.z, l1.w));
        }
        // B: x split on the fly. 16x64 packed entries.
        {
            int k2g = tid >> 4, n4 = (tid & 15) * 4;
            const float* be = &Bsrc[(k0 + 2 * k2g) * NPIX + n0 + n4];
            float4 e4 = *(const float4*)be;
            float4 o4 = *(const float4*)(be + NPIX);
            uint32_t h0,l0,h1,l1,h2,l2,h3,l3;
            split_pack(e4.x, o4.x, h0, l0); split_pack(e4.y, o4.y, h1, l1);
            split_pack(e4.z, o4.z, h2, l2); split_pack(e4.w, o4.w, h3, l3);
            *(uint4*)&Bh[k2g][n4] = make_uint4(h0, h1, h2, h3);
            *(uint4*)&Bl[k2g][n4] = make_uint4(l0, l1, l2, l3);
        }
        __syncthreads();
#pragma unroll
        for (int kk2 = 0; kk2 < 16; kk2 += 8) {
            uint32_t ah[2][4], al[2][4];
#pragma unroll
            for (int mi = 0; mi < 2; mi++) {
                int mr = wm + mi * 16;
                ah[mi][0]=Ah[mr+g  ][kk2+tig  ]; ah[mi][1]=Ah[mr+g+8][kk2+tig  ];
                ah[mi][2]=Ah[mr+g  ][kk2+tig+4]; ah[mi][3]=Ah[mr+g+8][kk2+tig+4];
                al[mi][0]=Al[mr+g  ][kk2+tig  ]; al[mi][1]=Al[mr+g+8][kk2+tig  ];
                al[mi][2]=Al[mr+g  ][kk2+tig+4]; al[mi][3]=Al[mr+g+8][kk2+tig+4];
            }
#pragma unroll
            for (int ni = 0; ni < 4; ni++) {
                uint32_t bh[2], bl[2];
                bh[0]=Bh[kk2+tig  ][wn+ni*8+g]; bh[1]=Bh[kk2+tig+4][wn+ni*8+g];
                bl[0]=Bl[kk2+tig  ][wn+ni*8+g]; bl[1]=Bl[kk2+tig+4][wn+ni*8+g];
#pragma unroll
                for (int mi = 0; mi < 2; mi++) {
                    mma16bf(c[mi][ni], ah[mi], bh);
                    mma16bf(c[mi][ni], ah[mi], bl);
                    mma16bf(c[mi][ni], al[mi], bh);
                }
            }
        }
        __syncthreads();
    }

    float* Cout = g_PRE[i][b];
#pragma unroll
    for (int mi = 0; mi < 2; mi++) {
#pragma unroll
        for (int ni = 0; ni < 4; ni++) {
            int row = wm + mi * 16 + g;
            int col = n0 + wn + ni * 8 + tig * 2;
            float b0 = g_bpre[i][row], b1 = g_bpre[i][row + 8];
            *(float2*)&Cout[row * NPIX + col] =
                make_float2(c[mi][ni][0] + b0, c[mi][ni][1] + b0);
            *(float2*)&Cout[(row + 8) * NPIX + col] =
                make_float2(c[mi][ni][2] + b1, c[mi][ni][3] + b1);
        }
    }
}

// ======================================================================
// k_etime_mma (unchanged from R3: tf32 3-term, small kernel)
// ======================================================================
__global__ void __launch_bounds__(512) k_etime_mma()
{
    int b = blockIdx.x / ETSPLIT, ks = blockIdx.x % ETSPLIT;
    int kbeg = ks * (NPIX / ETSPLIT);
    const float* __restrict__ T = g_PRE[2][b];
    const float* __restrict__ P = g_PRE[3][b];

    __shared__ uint32_t Ah[128][20], Al[128][20];
    __shared__ uint32_t Bh[128][20], Bl[128][20];

    int tid = threadIdx.x;
    int wid = tid >> 5, lane = tid & 31;
    int g = lane >> 2, tig = lane & 3;
    int wm = (wid & 3) * 32, wn = (wid >> 2) * 32;

    float c[2][4][4] = {};

    for (int k0 = kbeg; k0 < kbeg + NPIX / ETSPLIT; k0 += 16) {
        int m = tid >> 2, kq = (tid & 3) * 4;
        float4 t4 = *(const float4*)&T[m * NPIX + k0 + kq];
        float4 p4 = *(const float4*)&P[m * NPIX + k0 + kq];
        uint32_t h0,l0,h1,l1,h2,l2,h3,l3;
        f2t_split(t4.x,h0,l0); f2t_split(t4.y,h1,l1);
        f2t_split(t4.z,h2,l2); f2t_split(t4.w,h3,l3);
        Ah[m][kq+0]=h0; Ah[m][kq+1]=h1; Ah[m][kq+2]=h2; Ah[m][kq+3]=h3;
        Al[m][kq+0]=l0; Al[m][kq+1]=l1; Al[m][kq+2]=l2; Al[m][kq+3]=l3;
        f2t_split(p4.x,h0,l0); f2t_split(p4.y,h1,l1);
        f2t_split(p4.z,h2,l2); f2t_split(p4.w,h3,l3);
        Bh[m][kq+0]=h0; Bh[m][kq+1]=h1; Bh[m][kq+2]=h2; Bh[m][kq+3]=h3;
        Bl[m][kq+0]=l0; Bl[m][kq+1]=l1; Bl[m][kq+2]=l2; Bl[m][kq+3]=l3;
        __syncthreads();
#pragma unroll
        for (int kk = 0; kk < 16; kk += 8) {
            uint32_t ah[2][4], al[2][4];
#pragma unroll
            for (int mi = 0; mi < 2; mi++) {
                int mr = wm + mi * 16;
                ah[mi][0]=Ah[mr+g  ][kk+tig  ]; ah[mi][1]=Ah[mr+g+8][kk+tig  ];
                ah[mi][2]=Ah[mr+g  ][kk+tig+4]; ah[mi][3]=Ah[mr+g+8][kk+tig+4];
                al[mi][0]=Al[mr+g  ][kk+tig  ]; al[mi][1]=Al[mr+g+8][kk+tig  ];
                al[mi][2]=Al[mr+g  ][kk+tig+4]; al[mi][3]=Al[mr+g+8][kk+tig+4];
            }
#pragma unroll
            for (int ni = 0; ni < 4; ni++) {
                int nr = wn + ni * 8 + g;
                uint32_t bh[2], bl[2];
                bh[0]=Bh[nr][kk+tig]; bh[1]=Bh[nr][kk+tig+4];
                bl[0]=Bl[nr][kk+tig]; bl[1]=Bl[nr][kk+tig+4];
#pragma unroll
                for (int mi = 0; mi < 2; mi++) {
                    mma8(c[mi][ni], ah[mi], bh);
                    mma8(c[mi][ni], ah[mi], bl);
                    mma8(c[mi][ni], al[mi], bh);
                }
            }
        }
        __syncthreads();
    }

    float* outp = g_ETpart[b][ks];
#pragma unroll
    for (int mi = 0; mi < 2; mi++) {
#pragma unroll
        for (int ni = 0; ni < 4; ni++) {
            int row = wm + mi * 16 + g;
            int col = wn + ni * 8 + tig * 2;
            *(float2*)&outp[row * CI + col]       = make_float2(c[mi][ni][0], c[mi][ni][1]);
            *(float2*)&outp[(row + 8) * CI + col] = make_float2(c[mi][ni][2], c[mi][ni][3]);
        }
    }
}

__global__ void k_etreduce()
{
    int b = blockIdx.y, idx = blockIdx.x * 256 + threadIdx.x;
    float s = 0.f;
#pragma unroll
    for (int p = 0; p < ETSPLIT; p++) s += g_ETpart[b][p][idx];
    g_ET[b][idx] = s;
}

__global__ void k_softmax_time()
{
    int b = blockIdx.x, t = threadIdx.x;
    const float* ET = g_ET[b];
    float mx = -3.0e38f;
    for (int d = 0; d < CI; d++) mx = fmaxf(mx, ET[t * CI + d]);
    float s = 0.f;
    for (int d = 0; d < CI; d++) s += __expf(ET[t * CI + d] - mx);
    float rs = 1.f / s;
    for (int d = 0; d < CI; d++) g_A2[b][t * CI + d] = __expf(ET[t * CI + d] - mx) * rs;
    mx = -3.0e38f;
    for (int d = 0; d < CI; d++) mx = fmaxf(mx, ET[d * CI + t]);
    s = 0.f;
    for (int d = 0; d < CI; d++) s += __expf(ET[d * CI + t] - mx);
    rs = 1.f / s;
    for (int d = 0; d < CI; d++) g_A1[b][t * CI + d] = __expf(ET[d * CI + t] - mx) * rs;
}

// ======================================================================
// k_zgemm_mma (unchanged from R3)
// ======================================================================
__global__ void __launch_bounds__(512) k_zgemm_mma()
{
    int zi = blockIdx.z >> 2, b = blockIdx.z & 3;
    int n0 = blockIdx.x * 128;
    const float* __restrict__ Asrc = zi ? g_A2[b] : g_A1[b];
    const float* __restrict__ Bsrc = g_PRE[zi][b];

    __shared__ uint32_t As[128][36];
    __shared__ uint32_t Bs[32][136];

    int tid = threadIdx.x;
    int wid = tid >> 5, lane = tid & 31;
    int g = lane >> 2, tig = lane & 3;
    int wm = (wid & 3) * 32, wn = (wid >> 2) * 32;

    float c[2][4][4] = {};

    for (int k0 = 0; k0 < CI; k0 += 32) {
#pragma unroll
        for (int it = 0; it < 2; it++) {
            int v = tid + it * 512;
            int m = v >> 3, kq = (v & 7) * 4;
            float4 a4 = *(const float4*)&Asrc[m * CI + k0 + kq];
            As[m][kq+0]=f2t(a4.x); As[m][kq+1]=f2t(a4.y);
            As[m][kq+2]=f2t(a4.z); As[m][kq+3]=f2t(a4.w);
        }
#pragma unroll
        for (int it = 0; it < 2; it++) {
            int v = tid + it * 512;
            int kk = v >> 5, jq = (v & 31) * 4;
            float4 b4 = *(const float4*)&Bsrc[(k0 + kk) * NPIX + n0 + jq];
            Bs[kk][jq+0]=f2t(b4.x); Bs[kk][jq+1]=f2t(b4.y);
            Bs[kk][jq+2]=f2t(b4.z); Bs[kk][jq+3]=f2t(b4.w);
        }
        __syncthreads();
#pragma unroll
        for (int kk = 0; kk < 32; kk += 8) {
            uint32_t a[2][4];
#pragma unroll
            for (int mi = 0; mi < 2; mi++) {
                int mr = wm + mi * 16;
                a[mi][0]=As[mr+g  ][kk+tig  ]; a[mi][1]=As[mr+g+8][kk+tig  ];
                a[mi][2]=As[mr+g  ][kk+tig+4]; a[mi][3]=As[mr+g+8][kk+tig+4];
            }
#pragma unroll
            for (int ni = 0; ni < 4; ni++) {
                uint32_t bb[2];
                bb[0]=Bs[kk+tig  ][wn+ni*8+g];
                bb[1]=Bs[kk+tig+4][wn+ni*8+g];
                mma8(c[0][ni], a[0], bb);
                mma8(c[1][ni], a[1], bb);
            }
        }
        __syncthreads();
    }

    float* Zout = g_Z[zi][b];
#pragma unroll
    for (int mi = 0; mi < 2; mi++) {
#pragma unroll
        for (int ni = 0; ni < 4; ni++) {
            int row = wm + mi * 16 + g;
            int col = n0 + wn + ni * 8 + tig * 2;
            *(float2*)&Zout[row * NPIX + col]       = make_float2(c[mi][ni][0], c[mi][ni][1]);
            *(float2*)&Zout[(row + 8) * NPIX + col] = make_float2(c[mi][ni][2], c[mi][ni][3]);
        }
    }
}

// ======================================================================
// k_espace_bf16: E[n,m] = sum_k T[k,n] P[k,m]  (3-term bf16 m16n8k16)
// Block tile 128(n) x 64(m), 8 warps (4x2), K=128, chunk 32.
// A packed [k2][n] stride 136; B packed [k2][m] stride 72.
// ======================================================================
__global__ void __launch_bounds__(256) k_espace_bf16()
{
    int b = blockIdx.z;
    int row0 = blockIdx.y * 128, col0 = blockIdx.x * 64;
    const float* __restrict__ T = g_PRE[2][b];
    const float* __restrict__ P = g_PRE[3][b];

    __shared__ uint32_t Ah[16][136], Al[16][136];
    __shared__ uint32_t Bh[16][72],  Bl[16][72];

    int tid = threadIdx.x;
    int wid = tid >> 5, lane = tid & 31;
    int g = lane >> 2, tig = lane & 3;
    int wm = (wid & 3) * 32, wn = (wid >> 2) * 32;

    float c[2][4][4] = {};

    for (int k0 = 0; k0 < CI; k0 += 32) {
        // A: 16 k2-rows x 128 n
#pragma unroll
        for (int it = 0; it < 2; it++) {
            int v = tid + it * 256;
            int k2g = v >> 5, n4 = (v & 31) * 4;
            const float* te = &T[(k0 + 2 * k2g) * NPIX + row0 + n4];
            float4 e4 = *(const float4*)te;
            float4 o4 = *(const float4*)(te + NPIX);
            uint32_t h0,l0,h1,l1,h2,l2,h3,l3;
            split_pack(e4.x, o4.x, h0, l0); split_pack(e4.y, o4.y, h1, l1);
            split_pack(e4.z, o4.z, h2, l2); split_pack(e4.w, o4.w, h3, l3);
            *(uint4*)&Ah[k2g][n4] = make_uint4(h0, h1, h2, h3);
            *(uint4*)&Al[k2g][n4] = make_uint4(l0, l1, l2, l3);
        }
        // B: 16 k2-rows x 64 m
        {
            int k2g = tid >> 4, m4 = (tid & 15) * 4;
            const float* pe = &P[(k0 + 2 * k2g) * NPIX + col0 + m4];
            float4 e4 = *(const float4*)pe;
            float4 o4 = *(const float4*)(pe + NPIX);
            uint32_t h0,l0,h1,l1,h2,l2,h3,l3;
            split_pack(e4.x, o4.x, h0, l0); split_pack(e4.y, o4.y, h1, l1);
            split_pack(e4.z, o4.z, h2, l2); split_pack(e4.w, o4.w, h3, l3);
            *(uint4*)&Bh[k2g][m4] = make_uint4(h0, h1, h2, h3);
            *(uint4*)&Bl[k2g][m4] = make_uint4(l0, l1, l2, l3);
        }
        __syncthreads();
#pragma unroll
        for (int kk2 = 0; kk2 < 16; kk2 += 8) {
            uint32_t ah[2][4], al[2][4];
#pragma unroll
            for (int mi = 0; mi < 2; mi++) {
                int mr = wm + mi * 16;
                ah[mi][0] = Ah[kk2+tig  ][mr + g    ];
                ah[mi][1] = Ah[kk2+tig  ][mr + g + 8];
                ah[mi][2] = Ah[kk2+tig+4][mr + g    ];
                ah[mi][3] = Ah[kk2+tig+4][mr + g + 8];
                al[mi][0] = Al[kk2+tig  ][mr + g    ];
                al[mi][1] = Al[kk2+tig  ][mr + g + 8];
                al[mi][2] = Al[kk2+tig+4][mr + g    ];
                al[mi][3] = Al[kk2+tig+4][mr + g + 8];
            }
#pragma unroll
            for (int ni = 0; ni < 4; ni++) {
                uint32_t bh[2], bl[2];
                bh[0] = Bh[kk2+tig  ][wn + ni*8 + g];
                bh[1] = Bh[kk2+tig+4][wn + ni*8 + g];
                bl[0] = Bl[kk2+tig  ][wn + ni*8 + g];
                bl[1] = Bl[kk2+tig+4][wn + ni*8 + g];
#pragma unroll
                for (int mi = 0; mi < 2; mi++) {
                    mma16bf(c[mi][ni], ah[mi], bh);
                    mma16bf(c[mi][ni], ah[mi], bl);
                    mma16bf(c[mi][ni], al[mi], bh);
                }
            }
        }
        __syncthreads();
    }

    float* Ep = g_E[b];
#pragma unroll
    for (int mi = 0; mi < 2; mi++) {
#pragma unroll
        for (int ni = 0; ni < 4; ni++) {
            int row = row0 + wm + mi * 16 + g;
            int col = col0 + wn + ni * 8 + tig * 2;
            *(float2*)&Ep[row * NPIX + col]       = make_float2(c[mi][ni][0], c[mi][ni][1]);
            *(float2*)&Ep[(row + 8) * NPIX + col] = make_float2(c[mi][ni][2], c[mi][ni][3]);
        }
    }
}

// ---------------- e_space stats ----------------
__global__ void k_colpart()
{
    int b = blockIdx.z, ch = blockIdx.y;
    int m = blockIdx.x * 256 + threadIdx.x;
    const float* Ep = g_E[b];
    float mx = -3.0e38f, s = 0.f;
    int n0 = ch * (NPIX / NCHUNK);
    for (int n = n0; n < n0 + NPIX / NCHUNK; n++) {
        float v = Ep[n * NPIX + m];
        if (v > mx) { s = s * __expf(mx - v) + 1.f; mx = v; }
        else        { s += __expf(v - mx); }
    }
    g_pmax[b][ch][m] = mx;
    g_psum[b][ch][m] = s;
}

__global__ void k_colreduce()
{
    int b = blockIdx.y, m = blockIdx.x * 256 + threadIdx.x;
    float mx = -3.0e38f, s = 0.f;
#pragma unroll
    for (int ch = 0; ch < NCHUNK; ch++) {
        float pm = g_pmax[b][ch][m], ps = g_psum[b][ch][m];
        float nm = fmaxf(mx, pm);
        s = s * __expf(mx - nm) + ps * __expf(pm - nm);
        mx = nm;
    }
    g_colmax[b][m] = mx;
    g_colrsum[b][m] = 1.f / s;
}

__global__ void k_rowstats()
{
    int b = blockIdx.y;
    int n = blockIdx.x * 8 + (threadIdx.x >> 5);
    int lane = threadIdx.x & 31;
    const float* row = g_E[b] + n * NPIX;
    float mx = -3.0e38f, s = 0.f;
    for (int m = lane; m < NPIX; m += 32) {
        float v = row[m];
        if (v > mx) { s = s * __expf(mx - v) + 1.f; mx = v; }
        else        { s += __expf(v - mx); }
    }
#pragma unroll
    for (int off = 16; off; off >>= 1) {
        float om = __shfl_xor_sync(0xffffffffu, mx, off);
        float os = __shfl_xor_sync(0xffffffffu, s, off);
        float nm = fmaxf(mx, om);
        s = s * __expf(mx - nm) + os * __expf(om - nm);
        mx = nm;
    }
    if (lane == 0) { g_rowmax[b][n] = mx; g_rowrsum[b][n] = 1.f / s; }
}

// ======================================================================
// Y GEMMs (unchanged from R2/R3)
// ======================================================================
__global__ void __launch_bounds__(512) k_ygemm_mma()
{
    int yi = blockIdx.z >> 2, b = blockIdx.z & 3;
    int n0 = blockIdx.x * 128;
    const float* __restrict__ Zp = g_Z[yi][b];
    const float* __restrict__ Ep = g_E[b];
    const float* __restrict__ vmax = yi ? g_rowmax[b]  : g_colmax[b];
    const float* __restrict__ vrs  = yi ? g_rowrsum[b] : g_colrsum[b];

    __shared__ uint32_t As[128][36];
    __shared__ uint32_t BsRaw[128 * 36];
    __shared__ float s_max[128], s_rs[128];

    int tid = threadIdx.x;
    if (tid < 128) { s_max[tid] = vmax[n0 + tid]; s_rs[tid] = vrs[n0 + tid]; }
    __syncthreads();

    int wid = tid >> 5, lane = tid & 31;
    int g = lane >> 2, tig = lane & 3;
    int wm = (wid & 3) * 32, wn = (wid >> 2) * 32;

    float c[2][4][4] = {};

    for (int k0 = 0; k0 < NPIX; k0 += 32) {
#pragma unroll
        for (int it = 0; it < 2; it++) {
            int v = tid + it * 512;
            int m = v >> 3, kq = (v & 7) * 4;
            float4 z4 = *(const float4*)&Zp[m * NPIX + k0 + kq];
            As[m][kq+0] = f2t(z4.x); As[m][kq+1] = f2t(z4.y);
            As[m][kq+2] = f2t(z4.z); As[m][kq+3] = f2t(z4.w);
        }
        if (yi == 0) {
#pragma unroll
            for (int it = 0; it < 2; it++) {
                int v = tid + it * 512;
                int kk = v >> 5, jq = (v & 31) * 4;
                float4 e4 = *(const float4*)&Ep[(k0 + kk) * NPIX + n0 + jq];
                uint32_t* brow = &BsRaw[kk * 136];
                brow[jq+0] = f2t(__expf(e4.x - s_max[jq+0]));
                brow[jq+1] = f2t(__expf(e4.y - s_max[jq+1]));
                brow[jq+2] = f2t(__expf(e4.z - s_max[jq+2]));
                brow[jq+3] = f2t(__expf(e4.w - s_max[jq+3]));
            }
        } else {
#pragma unroll
            for (int it = 0; it < 2; it++) {
                int v = tid + it * 512;
                int j = v >> 3, kq = (v & 7) * 4;
                float4 e4 = *(const float4*)&Ep[(n0 + j) * NPIX + k0 + kq];
                float mxj = s_max[j];
                uint32_t* brow = &BsRaw[j * 36];
                brow[kq+0] = f2t(__expf(e4.x - mxj));
                brow[kq+1] = f2t(__expf(e4.y - mxj));
                brow[kq+2] = f2t(__expf(e4.z - mxj));
                brow[kq+3] = f2t(__expf(e4.w - mxj));
            }
        }
        __syncthreads();
#pragma unroll
        for (int kk = 0; kk < 32; kk += 8) {
            uint32_t a[2][4];
#pragma unroll
            for (int mi = 0; mi < 2; mi++) {
                int mr = wm + mi * 16;
                a[mi][0] = As[mr + g    ][kk + tig    ];
                a[mi][1] = As[mr + g + 8][kk + tig    ];
                a[mi][2] = As[mr + g    ][kk + tig + 4];
                a[mi][3] = As[mr + g + 8][kk + tig + 4];
            }
#pragma unroll
            for (int ni = 0; ni < 4; ni++) {
                uint32_t bb[2];
                if (yi == 0) {
                    bb[0] = BsRaw[(kk + tig    ) * 136 + wn + ni*8 + g];
                    bb[1] = BsRaw[(kk + tig + 4) * 136 + wn + ni*8 + g];
                } else {
                    bb[0] = BsRaw[(wn + ni*8 + g) * 36 + kk + tig    ];
                    bb[1] = BsRaw[(wn + ni*8 + g) * 36 + kk + tig + 4];
                }
                mma8(c[0][ni], a[0], bb);
                mma8(c[1][ni], a[1], bb);
            }
        }
        __syncthreads();
    }

    float* Yp = g_Y[yi][b];
#pragma unroll
    for (int mi = 0; mi < 2; mi++) {
#pragma unroll
        for (int ni = 0; ni < 4; ni++) {
            int row = wm + mi * 16 + g;
            int col = wn + ni * 8 + tig * 2;
            float r0 = s_rs[col], r1 = s_rs[col + 1];
            *(float2*)&Yp[row * NPIX + n0 + col] =
                make_float2(c[mi][ni][0] * r0, c[mi][ni][1] * r1);
            *(float2*)&Yp[(row + 8) * NPIX + n0 + col] =
                make_float2(c[mi][ni][2] * r0, c[mi][ni][3] * r1);
        }
    }
}

// ======================================================================
// k_post_mma (unchanged from R3)
// ======================================================================
__global__ void __launch_bounds__(512) k_post_mma(const float* __restrict__ x1,
                                                  const float* __restrict__ x2,
                                                  float* __restrict__ out)
{
    int i = blockIdx.z >> 2, b = blockIdx.z & 3;
    int m0 = blockIdx.y * 128, n0 = blockIdx.x * 128;
    const float* __restrict__ Asrc = g_Wpost[i];
    const float* __restrict__ Bsrc = g_Y[i][b];

    __shared__ uint32_t As[128][36];
    __shared__ uint32_t Bs[32][136];

    int tid = threadIdx.x;
    int wid = tid >> 5, lane = tid & 31;
    int g = lane >> 2, tig = lane & 3;
    int wm = (wid & 3) * 32, wn = (wid >> 2) * 32;

    float c[2][4][4] = {};

    for (int k0 = 0; k0 < CI; k0 += 32) {
#pragma unroll
        for (int it = 0; it < 2; it++) {
            int v = tid + it * 512;
            int m = v >> 3, kq = (v & 7) * 4;
            float4 a4 = *(const float4*)&Asrc[(m0 + m) * CI + k0 + kq];
            As[m][kq+0]=f2t(a4.x); As[m][kq+1]=f2t(a4.y);
            As[m][kq+2]=f2t(a4.z); As[m][kq+3]=f2t(a4.w);
        }
#pragma unroll
        for (int it = 0; it < 2; it++) {
            int v = tid + it * 512;
            int kk = v >> 5, jq = (v & 31) * 4;
            float4 b4 = *(const float4*)&Bsrc[(k0 + kk) * NPIX + n0 + jq];
            Bs[kk][jq+0]=f2t(b4.x); Bs[kk][jq+1]=f2t(b4.y);
            Bs[kk][jq+2]=f2t(b4.z); Bs[kk][jq+3]=f2t(b4.w);
        }
        __syncthreads();
#pragma unroll
        for (int kk = 0; kk < 32; kk += 8) {
            uint32_t a[2][4];
#pragma unroll
            for (int mi = 0; mi < 2; mi++) {
                int mr = wm + mi * 16;
                a[mi][0]=As[mr+g  ][kk+tig  ]; a[mi][1]=As[mr+g+8][kk+tig  ];
                a[mi][2]=As[mr+g  ][kk+tig+4]; a[mi][3]=As[mr+g+8][kk+tig+4];
            }
#pragma unroll
            for (int ni = 0; ni < 4; ni++) {
                uint32_t bb[2];
                bb[0]=Bs[kk+tig  ][wn+ni*8+g];
                bb[1]=Bs[kk+tig+4][wn+ni*8+g];
                mma8(c[0][ni], a[0], bb);
                mma8(c[1][ni], a[1], bb);
            }
        }
        __syncthreads();
    }

    const float* xs = (i ? x2 : x1) + b * CC * NPIX;
    float* op = out + (size_t)i * BATCH * CC * NPIX + (size_t)b * CC * NPIX;
#pragma unroll
    for (int mi = 0; mi < 2; mi++) {
#pragma unroll
        for (int ni = 0; ni < 4; ni++) {
            int row = m0 + wm + mi * 16 + g;
            int col = n0 + wn + ni * 8 + tig * 2;
            float b0 = g_bpost[i][row], b1 = g_bpost[i][row + 8];
            float2 r0 = *(const float2*)&xs[row * NPIX + col];
            float2 r1 = *(const float2*)&xs[(row + 8) * NPIX + col];
            *(float2*)&op[row * NPIX + col] =
                make_float2(c[mi][ni][0] + b0 + r0.x, c[mi][ni][1] + b0 + r0.y);
            *(float2*)&op[(row + 8) * NPIX + col] =
                make_float2(c[mi][ni][2] + b1 + r1.x, c[mi][ni][3] + b1 + r1.y);
        }
    }
}

// ---------------- launcher ----------------
extern "C" void kernel_launch(void* const* d_in, const int* in_sizes, int n_in,
                              void* d_out, int out_size)
{
    const float* x1      = (const float*)d_in[0];
    const float* x2      = (const float*)d_in[1];
    const float* bn_pre  = (const float*)d_in[2];
    const float* w_pre   = (const float*)d_in[3];
    const float* b_pre   = (const float*)d_in[4];
    const float* w_post  = (const float*)d_in[5];
    const float* b_post  = (const float*)d_in[6];
    const float* bn_post = (const float*)d_in[7];
    float* out = (float*)d_out;

    k_fold<<<2, 512>>>(bn_pre, w_pre, b_pre, w_post, b_post, bn_post);
    k_pre_bf16<<<dim3(36, 1, 16), 256>>>(x1, x2);
    k_etime_mma<<<BATCH * ETSPLIT, 512>>>();
    k_etreduce<<<dim3(64, BATCH), 256>>>();
    k_softmax_time<<<BATCH, 128>>>();
    k_espace_bf16<<<dim3(36, 18, BATCH), 256>>>();
    k_zgemm_mma<<<dim3(18, 1, 8), 512>>>();
    k_colpart<<<dim3(9, NCHUNK, BATCH), 256>>>();
    k_colreduce<<<dim3(9, BATCH), 256>>>();
    k_rowstats<<<dim3(288, BATCH), 256>>>();
    k_ygemm_mma<<<dim3(18, 1, 8), 512>>>();
    k_post_mma<<<dim3(18, 2, 8), 512>>>(x1, x2, out);
}

// round 5
// speedup vs baseline: 1.0829x; 1.0061x over previous
#include <cuda_runtime.h>
#include <cuda_bf16.h>
#include <math.h>
#include <stdint.h>

#define BATCH 4
#define CC 256
#define CI 128
#define NPIX 2304
#define BNEPS 1e-5f
#define NCHUNK 18
#define ETSPLIT 18

// ---------------- scratch ----------------
__device__ float g_PRE[4][BATCH][CI*NPIX];
__device__ float g_ETpart[BATCH][ETSPLIT][CI*CI];
__device__ float g_ET[BATCH][CI*CI];
__device__ float g_A1[BATCH][CI*CI];
__device__ float g_A2[BATCH][CI*CI];
__device__ float g_E[BATCH][NPIX*NPIX];
__device__ float g_Z[2][BATCH][CI*NPIX];
__device__ float g_Y[2][BATCH][CI*NPIX];
__device__ float g_colmax[BATCH][NPIX];
__device__ float g_colrsum[BATCH][NPIX];
__device__ float g_rowmax[BATCH][NPIX];
__device__ float g_rowrsum[BATCH][NPIX];
__device__ float g_pmax[BATCH][NCHUNK][NPIX];
__device__ float g_psum[BATCH][NCHUNK][NPIX];
__device__ float g_WpreH[4][CI*CC];
__device__ float g_WpreL[4][CI*CC];
__device__ float g_bpre[4][CI];
__device__ float g_Wpost[2][CC*CI];
__device__ float g_bpost[2][CC];

// ---------------- helpers ----------------
__device__ __forceinline__ uint32_t f2t(float x) {
    uint32_t r;
    asm("cvt.rna.tf32.f32 %0, %1;" : "=r"(r) : "f"(x));
    return r;
}
__device__ __forceinline__ void mma8(float c[4], const uint32_t a[4], const uint32_t b[2]) {
    asm volatile(
        "mma.sync.aligned.m16n8k8.row.col.f32.tf32.tf32.f32 "
        "{%0,%1,%2,%3}, {%4,%5,%6,%7}, {%8,%9}, {%0,%1,%2,%3};"
        : "+f"(c[0]), "+f"(c[1]), "+f"(c[2]), "+f"(c[3])
        : "r"(a[0]), "r"(a[1]), "r"(a[2]), "r"(a[3]), "r"(b[0]), "r"(b[1]));
}
__device__ __forceinline__ uint32_t pack_bf(float e, float o) {
    uint32_t r;
    asm("cvt.rn.bf16x2.f32 %0, %1, %2;" : "=r"(r) : "f"(o), "f"(e));
    return r;
}
__device__ __forceinline__ float bf_round(float x) {
    return __bfloat162float(__float2bfloat16(x));
}
__device__ __forceinline__ void mma16bf(float c[4], const uint32_t a[4], const uint32_t b[2]) {
    asm volatile(
        "mma.sync.aligned.m16n8k16.row.col.f32.bf16.bf16.f32 "
        "{%0,%1,%2,%3}, {%4,%5,%6,%7}, {%8,%9}, {%0,%1,%2,%3};"
        : "+f"(c[0]), "+f"(c[1]), "+f"(c[2]), "+f"(c[3])
        : "r"(a[0]), "r"(a[1]), "r"(a[2]), "r"(a[3]), "r"(b[0]), "r"(b[1]));
}
__device__ __forceinline__ void split_pack(float e, float o, uint32_t& hp, uint32_t& lp) {
    float eh = bf_round(e), oh = bf_round(o);
    hp = pack_bf(eh, oh);
    lp = pack_bf(e - eh, o - oh);
}

// ---------------- BN folding ----------------
__global__ void k_fold(const float* __restrict__ bn_pre, const float* __restrict__ w_pre,
                       const float* __restrict__ b_pre, const float* __restrict__ w_post,
                       const float* __restrict__ b_post, const float* __restrict__ bn_post)
{
    int tid = threadIdx.x;
    if (blockIdx.x == 0) {
        int i = tid >> 7, o = tid & 127;
        const float* bp = bn_pre + i * 4 * CC;
        const float* w  = w_pre + (i * CI + o) * CC;
        float acc = b_pre[i * CI + o];
        for (int c = 0; c < CC; c++) {
            float s = bp[c] * rsqrtf(bp[3 * CC + c] + BNEPS);
            float t = bp[CC + c] - bp[2 * CC + c] * s;
            float wv = w[c] * s;
            float h = bf_round(wv);
            g_WpreH[i][o * CC + c] = h;
            g_WpreL[i][o * CC + c] = wv - h;
            acc += w[c] * t;
        }
        g_bpre[i][o] = acc;
    } else {
        int i = tid >> 8, o = tid & 255;
        const float* bp = bn_post + i * 4 * CC;
        float s = bp[o] * rsqrtf(bp[3 * CC + o] + BNEPS);
        const float* w = w_post + (i * CC + o) * CI;
        for (int c = 0; c < CI; c++)
            g_Wpost[i][o * CI + c] = w[c] * s;
        g_bpost[i][o] = b_post[i * CC + o] * s + bp[CC + o] - bp[2 * CC + o] * s;
    }
}

// ======================================================================
// k_pre_bf16: PRE = W@x + b. 3-term bf16, pipelined. 128x64 tile, 256 thr.
// ======================================================================
__global__ void __launch_bounds__(256) k_pre_bf16(const float* __restrict__ x1,
                                                  const float* __restrict__ x2)
{
    int i = blockIdx.z >> 2, b = blockIdx.z & 3;
    int n0 = blockIdx.x * 64;
    const float* __restrict__ AHf = g_WpreH[i];
    const float* __restrict__ ALf = g_WpreL[i];
    const float* __restrict__ Bsrc = ((i & 1) ? x2 : x1) + b * CC * NPIX;

    __shared__ uint32_t Ah[128][20], Al[128][20], Bh[16][72], Bl[16][72];

    int tid = threadIdx.x;
    int wid = tid >> 5, lane = tid & 31;
    int g = lane >> 2, tig = lane & 3;
    int wm = (wid & 3) * 32, wn = (wid >> 2) * 32;

    int am = tid >> 2, akq = (tid & 3) * 8;
    int bk2 = tid >> 4, bn4 = (tid & 15) * 4;

    float4 sh0[2], sh1[2], sl0[2], sl1[2], sbe, sbo;
    float c[2][4][4] = {};

    auto loadT = [&](int k0) {
#pragma unroll
        for (int it = 0; it < 2; it++) {
            int m = am + it * 64;
            sh0[it] = *(const float4*)&AHf[m * CC + k0 + akq];
            sh1[it] = *(const float4*)&AHf[m * CC + k0 + akq + 4];
            sl0[it] = *(const float4*)&ALf[m * CC + k0 + akq];
            sl1[it] = *(const float4*)&ALf[m * CC + k0 + akq + 4];
        }
        const float* be = &Bsrc[(k0 + 2 * bk2) * NPIX + n0 + bn4];
        sbe = *(const float4*)be;
        sbo = *(const float4*)(be + NPIX);
    };
    auto storeT = [&]() {
#pragma unroll
        for (int it = 0; it < 2; it++) {
            int m = am + it * 64, kq2 = akq >> 1;
            *(uint4*)&Ah[m][kq2] = make_uint4(
                pack_bf(sh0[it].x, sh0[it].y), pack_bf(sh0[it].z, sh0[it].w),
                pack_bf(sh1[it].x, sh1[it].y), pack_bf(sh1[it].z, sh1[it].w));
            *(uint4*)&Al[m][kq2] = make_uint4(
                pack_bf(sl0[it].x, sl0[it].y), pack_bf(sl0[it].z, sl0[it].w),
                pack_bf(sl1[it].x, sl1[it].y), pack_bf(sl1[it].z, sl1[it].w));
        }
        uint32_t h0,l0,h1,l1,h2,l2,h3,l3;
        split_pack(sbe.x, sbo.x, h0, l0); split_pack(sbe.y, sbo.y, h1, l1);
        split_pack(sbe.z, sbo.z, h2, l2); split_pack(sbe.w, sbo.w, h3, l3);
        *(uint4*)&Bh[bk2][bn4] = make_uint4(h0, h1, h2, h3);
        *(uint4*)&Bl[bk2][bn4] = make_uint4(l0, l1, l2, l3);
    };

    loadT(0); storeT(); __syncthreads();
    for (int t = 0; t < 8; t++) {
        if (t < 7) loadT((t + 1) * 32);
#pragma unroll
        for (int kk2 = 0; kk2 < 16; kk2 += 8) {
            uint32_t ah[2][4], al[2][4];
#pragma unroll
            for (int mi = 0; mi < 2; mi++) {
                int mr = wm + mi * 16;
                ah[mi][0]=Ah[mr+g  ][kk2+tig  ]; ah[mi][1]=Ah[mr+g+8][kk2+tig  ];
                ah[mi][2]=Ah[mr+g  ][kk2+tig+4]; ah[mi][3]=Ah[mr+g+8][kk2+tig+4];
                al[mi][0]=Al[mr+g  ][kk2+tig  ]; al[mi][1]=Al[mr+g+8][kk2+tig  ];
                al[mi][2]=Al[mr+g  ][kk2+tig+4]; al[mi][3]=Al[mr+g+8][kk2+tig+4];
            }
#pragma unroll
            for (int ni = 0; ni < 4; ni++) {
                uint32_t bh[2], bl[2];
                bh[0]=Bh[kk2+tig  ][wn+ni*8+g]; bh[1]=Bh[kk2+tig+4][wn+ni*8+g];
                bl[0]=Bl[kk2+tig  ][wn+ni*8+g]; bl[1]=Bl[kk2+tig+4][wn+ni*8+g];
#pragma unroll
                for (int mi = 0; mi < 2; mi++) {
                    mma16bf(c[mi][ni], ah[mi], bh);
                    mma16bf(c[mi][ni], ah[mi], bl);
                    mma16bf(c[mi][ni], al[mi], bh);
                }
            }
        }
        __syncthreads();
        if (t < 7) storeT();
        __syncthreads();
    }

    float* Cout = g_PRE[i][b];
#pragma unroll
    for (int mi = 0; mi < 2; mi++) {
#pragma unroll
        for (int ni = 0; ni < 4; ni++) {
            int row = wm + mi * 16 + g;
            int col = n0 + wn + ni * 8 + tig * 2;
            float b0 = g_bpre[i][row], b1 = g_bpre[i][row + 8];
            *(float2*)&Cout[row * NPIX + col] =
                make_float2(c[mi][ni][0] + b0, c[mi][ni][1] + b0);
            *(float2*)&Cout[(row + 8) * NPIX + col] =
                make_float2(c[mi][ni][2] + b1, c[mi][ni][3] + b1);
        }
    }
}

// ======================================================================
// k_etime_bf16: ETpart = T@P^T over K-slice. 3-term bf16, pipelined.
// Block 128x64, 256 thr. grid (2 ntiles, ETSPLIT, BATCH)
// ======================================================================
__global__ void __launch_bounds__(256) k_etime_bf16()
{
    int b = blockIdx.z, ks = blockIdx.y;
    int n0 = blockIdx.x * 64;
    int kbeg = ks * (NPIX / ETSPLIT);
    const float* __restrict__ Tm = g_PRE[2][b];
    const float* __restrict__ Pm = g_PRE[3][b];

    __shared__ uint32_t Ah[128][20], Al[128][20], Bh[64][20], Bl[64][20];

    int tid = threadIdx.x;
    int wid = tid >> 5, lane = tid & 31;
    int g = lane >> 2, tig = lane & 3;
    int wm = (wid & 3) * 32, wn = (wid >> 2) * 32;

    int am = tid >> 1, ak = (tid & 1) * 16;
    int bn = tid >> 2, bk = (tid & 3) * 8;

    float4 sA[4], sB[2];
    float c[2][4][4] = {};

    auto loadT = [&](int k0) {
#pragma unroll
        for (int q = 0; q < 4; q++) sA[q] = *(const float4*)&Tm[am * NPIX + k0 + ak + q * 4];
#pragma unroll
        for (int q = 0; q < 2; q++) sB[q] = *(const float4*)&Pm[(n0 + bn) * NPIX + k0 + bk + q * 4];
    };
    auto storeT = [&]() {
#pragma unroll
        for (int q = 0; q < 4; q++) {
            uint32_t h0,l0,h1,l1;
            split_pack(sA[q].x, sA[q].y, h0, l0);
            split_pack(sA[q].z, sA[q].w, h1, l1);
            int k2 = (ak >> 1) + q * 2;
            Ah[am][k2] = h0; Ah[am][k2+1] = h1;
            Al[am][k2] = l0; Al[am][k2+1] = l1;
        }
#pragma unroll
        for (int q = 0; q < 2; q++) {
            uint32_t h0,l0,h1,l1;
            split_pack(sB[q].x, sB[q].y, h0, l0);
            split_pack(sB[q].z, sB[q].w, h1, l1);
            int k2 = (bk >> 1) + q * 2;
            Bh[bn][k2] = h0; Bh[bn][k2+1] = h1;
            Bl[bn][k2] = l0; Bl[bn][k2+1] = l1;
        }
    };

    loadT(kbeg); storeT(); __syncthreads();
    for (int t = 0; t < 4; t++) {
        if (t < 3) loadT(kbeg + (t + 1) * 32);
#pragma unroll
        for (int kk2 = 0; kk2 < 16; kk2 += 8) {
            uint32_t ah[2][4], al[2][4];
#pragma unroll
            for (int mi = 0; mi < 2; mi++) {
                int mr = wm + mi * 16;
                ah[mi][0]=Ah[mr+g  ][kk2+tig  ]; ah[mi][1]=Ah[mr+g+8][kk2+tig  ];
                ah[mi][2]=Ah[mr+g  ][kk2+tig+4]; ah[mi][3]=Ah[mr+g+8][kk2+tig+4];
                al[mi][0]=Al[mr+g  ][kk2+tig  ]; al[mi][1]=Al[mr+g+8][kk2+tig  ];
                al[mi][2]=Al[mr+g  ][kk2+tig+4]; al[mi][3]=Al[mr+g+8][kk2+tig+4];
            }
#pragma unroll
            for (int ni = 0; ni < 4; ni++) {
                int nr = wn + ni * 8 + g;
                uint32_t bh[2], bl[2];
                bh[0]=Bh[nr][kk2+tig]; bh[1]=Bh[nr][kk2+tig+4];
                bl[0]=Bl[nr][kk2+tig]; bl[1]=Bl[nr][kk2+tig+4];
#pragma unroll
                for (int mi = 0; mi < 2; mi++) {
                    mma16bf(c[mi][ni], ah[mi], bh);
                    mma16bf(c[mi][ni], ah[mi], bl);
                    mma16bf(c[mi][ni], al[mi], bh);
                }
            }
        }
        __syncthreads();
        if (t < 3) storeT();
        __syncthreads();
    }

    float* outp = g_ETpart[b][ks];
#pragma unroll
    for (int mi = 0; mi < 2; mi++) {
#pragma unroll
        for (int ni = 0; ni < 4; ni++) {
            int row = wm + mi * 16 + g;
            int col = n0 + wn + ni * 8 + tig * 2;
            *(float2*)&outp[row * CI + col]       = make_float2(c[mi][ni][0], c[mi][ni][1]);
            *(float2*)&outp[(row + 8) * CI + col] = make_float2(c[mi][ni][2], c[mi][ni][3]);
        }
    }
}

__global__ void k_etreduce()
{
    int b = blockIdx.y, idx = blockIdx.x * 256 + threadIdx.x;
    float s = 0.f;
#pragma unroll
    for (int p = 0; p < ETSPLIT; p++) s += g_ETpart[b][p][idx];
    g_ET[b][idx] = s;
}

__global__ void k_softmax_time()
{
    int b = blockIdx.x, t = threadIdx.x;
    const float* ET = g_ET[b];
    float mx = -3.0e38f;
    for (int d = 0; d < CI; d++) mx = fmaxf(mx, ET[t * CI + d]);
    float s = 0.f;
    for (int d = 0; d < CI; d++) s += __expf(ET[t * CI + d] - mx);
    float rs = 1.f / s;
    for (int d = 0; d < CI; d++) g_A2[b][t * CI + d] = __expf(ET[t * CI + d] - mx) * rs;
    mx = -3.0e38f;
    for (int d = 0; d < CI; d++) mx = fmaxf(mx, ET[d * CI + t]);
    s = 0.f;
    for (int d = 0; d < CI; d++) s += __expf(ET[d * CI + t] - mx);
    rs = 1.f / s;
    for (int d = 0; d < CI; d++) g_A1[b][t * CI + d] = __expf(ET[d * CI + t] - mx) * rs;
}

// ======================================================================
// k_espace_bf16: E = T^T@P. 3-term bf16, pipelined. 128x64 tile, 256 thr.
// ======================================================================
__global__ void __launch_bounds__(256) k_espace_bf16()
{
    int b = blockIdx.z;
    int row0 = blockIdx.y * 128, col0 = blockIdx.x * 64;
    const float* __restrict__ T = g_PRE[2][b];
    const float* __restrict__ P = g_PRE[3][b];

    __shared__ uint32_t Ah[16][136], Al[16][136];
    __shared__ uint32_t Bh[16][72],  Bl[16][72];

    int tid = threadIdx.x;
    int wid = tid >> 5, lane = tid & 31;
    int g = lane >> 2, tig = lane & 3;
    int wm = (wid & 3) * 32, wn = (wid >> 2) * 32;

    int ak2 = tid >> 5, an4 = (tid & 31) * 4;  // + it*8 rows
    int bk2 = tid >> 4, bm4 = (tid & 15) * 4;

    float4 sAe[2], sAo[2], sBe, sBo;
    float c[2][4][4] = {};

    auto loadT = [&](int k0) {
#pragma unroll
        for (int it = 0; it < 2; it++) {
            const float* te = &T[(k0 + 2 * (ak2 + it * 8)) * NPIX + row0 + an4];
            sAe[it] = *(const float4*)te;
            sAo[it] = *(const float4*)(te + NPIX);
        }
        const float* pe = &P[(k0 + 2 * bk2) * NPIX + col0 + bm4];
        sBe = *(const float4*)pe;
        sBo = *(const float4*)(pe + NPIX);
    };
    auto storeT = [&]() {
#pragma unroll
        for (int it = 0; it < 2; it++) {
            uint32_t h0,l0,h1,l1,h2,l2,h3,l3;
            split_pack(sAe[it].x, sAo[it].x, h0, l0); split_pack(sAe[it].y, sAo[it].y, h1, l1);
            split_pack(sAe[it].z, sAo[it].z, h2, l2); split_pack(sAe[it].w, sAo[it].w, h3, l3);
            int r = ak2 + it * 8;
            *(uint4*)&Ah[r][an4] = make_uint4(h0, h1, h2, h3);
            *(uint4*)&Al[r][an4] = make_uint4(l0, l1, l2, l3);
        }
        uint32_t h0,l0,h1,l1,h2,l2,h3,l3;
        split_pack(sBe.x, sBo.x, h0, l0); split_pack(sBe.y, sBo.y, h1, l1);
        split_pack(sBe.z, sBo.z, h2, l2); split_pack(sBe.w, sBo.w, h3, l3);
        *(uint4*)&Bh[bk2][bm4] = make_uint4(h0, h1, h2, h3);
        *(uint4*)&Bl[bk2][bm4] = make_uint4(l0, l1, l2, l3);
    };

    loadT(0); storeT(); __syncthreads();
    for (int t = 0; t < 4; t++) {
        if (t < 3) loadT((t + 1) * 32);
#pragma unroll
        for (int kk2 = 0; kk2 < 16; kk2 += 8) {
            uint32_t ah[2][4], al[2][4];
#pragma unroll
            for (int mi = 0; mi < 2; mi++) {
                int mr = wm + mi * 16;
                ah[mi][0] = Ah[kk2+tig  ][mr + g    ];
                ah[mi][1] = Ah[kk2+tig  ][mr + g + 8];
                ah[mi][2] = Ah[kk2+tig+4][mr + g    ];
                ah[mi][3] = Ah[kk2+tig+4][mr + g + 8];
                al[mi][0] = Al[kk2+tig  ][mr + g    ];
                al[mi][1] = Al[kk2+tig  ][mr + g + 8];
                al[mi][2] = Al[kk2+tig+4][mr + g    ];
                al[mi][3] = Al[kk2+tig+4][mr + g + 8];
            }
#pragma unroll
            for (int ni = 0; ni < 4; ni++) {
                uint32_t bh[2], bl[2];
                bh[0] = Bh[kk2+tig  ][wn + ni*8 + g];
                bh[1] = Bh[kk2+tig+4][wn + ni*8 + g];
                bl[0] = Bl[kk2+tig  ][wn + ni*8 + g];
                bl[1] = Bl[kk2+tig+4][wn + ni*8 + g];
#pragma unroll
                for (int mi = 0; mi < 2; mi++) {
                    mma16bf(c[mi][ni], ah[mi], bh);
                    mma16bf(c[mi][ni], ah[mi], bl);
                    mma16bf(c[mi][ni], al[mi], bh);
                }
            }
        }
        __syncthreads();
        if (t < 3) storeT();
        __syncthreads();
    }

    float* Ep = g_E[b];
#pragma unroll
    for (int mi = 0; mi < 2; mi++) {
#pragma unroll
        for (int ni = 0; ni < 4; ni++) {
            int row = row0 + wm + mi * 16 + g;
            int col = col0 + wn + ni * 8 + tig * 2;
            *(float2*)&Ep[row * NPIX + col]       = make_float2(c[mi][ni][0], c[mi][ni][1]);
            *(float2*)&Ep[(row + 8) * NPIX + col] = make_float2(c[mi][ni][2], c[mi][ni][3]);
        }
    }
}

// ---------------- e_space stats ----------------
__global__ void k_colpart()
{
    int b = blockIdx.z, ch = blockIdx.y;
    int m = blockIdx.x * 256 + threadIdx.x;
    const float* Ep = g_E[b];
    float mx = -3.0e38f, s = 0.f;
    int n0 = ch * (NPIX / NCHUNK);
    for (int n = n0; n < n0 + NPIX / NCHUNK; n++) {
        float v = Ep[n * NPIX + m];
        if (v > mx) { s = s * __expf(mx - v) + 1.f; mx = v; }
        else        { s += __expf(v - mx); }
    }
    g_pmax[b][ch][m] = mx;
    g_psum[b][ch][m] = s;
}

__global__ void k_colreduce()
{
    int b = blockIdx.y, m = blockIdx.x * 256 + threadIdx.x;
    float mx = -3.0e38f, s = 0.f;
#pragma unroll
    for (int ch = 0; ch < NCHUNK; ch++) {
        float pm = g_pmax[b][ch][m], ps = g_psum[b][ch][m];
        float nm = fmaxf(mx, pm);
        s = s * __expf(mx - nm) + ps * __expf(pm - nm);
        mx = nm;
    }
    g_colmax[b][m] = mx;
    g_colrsum[b][m] = 1.f / s;
}

__global__ void k_rowstats()
{
    int b = blockIdx.y;
    int n = blockIdx.x * 8 + (threadIdx.x >> 5);
    int lane = threadIdx.x & 31;
    const float* row = g_E[b] + n * NPIX;
    float mx = -3.0e38f, s = 0.f;
    for (int m = lane; m < NPIX; m += 32) {
        float v = row[m];
        if (v > mx) { s = s * __expf(mx - v) + 1.f; mx = v; }
        else        { s += __expf(v - mx); }
    }
#pragma unroll
    for (int off = 16; off; off >>= 1) {
        float om = __shfl_xor_sync(0xffffffffu, mx, off);
        float os = __shfl_xor_sync(0xffffffffu, s, off);
        float nm = fmaxf(mx, om);
        s = s * __expf(mx - nm) + os * __expf(om - nm);
        mx = nm;
    }
    if (lane == 0) { g_rowmax[b][n] = mx; g_rowrsum[b][n] = 1.f / s; }
}

// ======================================================================
// k_zgemm_mma: Z = A@G. tf32 single-pass, pipelined, 128x64, 256 thr.
// ======================================================================
__global__ void __launch_bounds__(256) k_zgemm_mma()
{
    int zi = blockIdx.z >> 2, b = blockIdx.z & 3;
    int n0 = blockIdx.x * 64;
    const float* __restrict__ Asrc = zi ? g_A2[b] : g_A1[b];
    const float* __restrict__ Bsrc = g_PRE[zi][b];

    __shared__ uint32_t As[128][36];
    __shared__ uint32_t Bs[32][72];

    int tid = threadIdx.x;
    int wid = tid >> 5, lane = tid & 31;
    int g = lane >> 2, tig = lane & 3;
    int wm = (wid & 3) * 32, wn = (wid >> 2) * 32;

    int am = tid >> 1, ak = (tid & 1) * 16;
    int bkk = tid >> 3, bjq = (tid & 7) * 8;

    float4 sA[4], sB[2];
    float c[2][4][4] = {};

    auto loadT = [&](int k0) {
#pragma unroll
        for (int q = 0; q < 4; q++) sA[q] = *(const float4*)&Asrc[am * CI + k0 + ak + q * 4];
#pragma unroll
        for (int q = 0; q < 2; q++) sB[q] = *(const float4*)&Bsrc[(k0 + bkk) * NPIX + n0 + bjq + q * 4];
    };
    auto storeT = [&]() {
#pragma unroll
        for (int q = 0; q < 4; q++) {
            *(uint4*)&As[am][ak + q * 4] = make_uint4(
                f2t(sA[q].x), f2t(sA[q].y), f2t(sA[q].z), f2t(sA[q].w));
        }
#pragma unroll
        for (int q = 0; q < 2; q++) {
            *(uint4*)&Bs[bkk][bjq + q * 4] = make_uint4(
                f2t(sB[q].x), f2t(sB[q].y), f2t(sB[q].z), f2t(sB[q].w));
        }
    };

    loadT(0); storeT(); __syncthreads();
    for (int t = 0; t < 4; t++) {
        if (t < 3) loadT((t + 1) * 32);
#pragma unroll
        for (int kk = 0; kk < 32; kk += 8) {
            uint32_t a[2][4];
#pragma unroll
            for (int mi = 0; mi < 2; mi++) {
                int mr = wm + mi * 16;
                a[mi][0]=As[mr+g  ][kk+tig  ]; a[mi][1]=As[mr+g+8][kk+tig  ];
                a[mi][2]=As[mr+g  ][kk+tig+4]; a[mi][3]=As[mr+g+8][kk+tig+4];
            }
#pragma unroll
            for (int ni = 0; ni < 4; ni++) {
                uint32_t bb[2];
                bb[0]=Bs[kk+tig  ][wn+ni*8+g];
                bb[1]=Bs[kk+tig+4][wn+ni*8+g];
                mma8(c[0][ni], a[0], bb);
                mma8(c[1][ni], a[1], bb);
            }
        }
        __syncthreads();
        if (t < 3) storeT();
        __syncthreads();
    }

    float* Zout = g_Z[zi][b];
#pragma unroll
    for (int mi = 0; mi < 2; mi++) {
#pragma unroll
        for (int ni = 0; ni < 4; ni++) {
            int row = wm + mi * 16 + g;
            int col = n0 + wn + ni * 8 + tig * 2;
            *(float2*)&Zout[row * NPIX + col]       = make_float2(c[mi][ni][0], c[mi][ni][1]);
            *(float2*)&Zout[(row + 8) * NPIX + col] = make_float2(c[mi][ni][2], c[mi][ni][3]);
        }
    }
}

// ======================================================================
// k_ygemm_mma: y = Z @ softmaxed(E). tf32, pipelined, fused exp.
// 128x64 tile, 256 thr, T=72 chunks.
// ======================================================================
__global__ void __launch_bounds__(256) k_ygemm_mma()
{
    int yi = blockIdx.z >> 2, b = blockIdx.z & 3;
    int n0 = blockIdx.x * 64;
    const float* __restrict__ Zp = g_Z[yi][b];
    const float* __restrict__ Ep = g_E[b];
    const float* __restrict__ vmax = yi ? g_rowmax[b]  : g_colmax[b];
    const float* __restrict__ vrs  = yi ? g_rowrsum[b] : g_colrsum[b];

    __shared__ uint32_t As[128][36];
    __shared__ uint32_t Bs[2304];   // yi=0: [32][72]; yi=1: [64][36]
    __shared__ float s_max[64], s_rs[64];

    int tid = threadIdx.x;
    if (tid < 64) { s_max[tid] = vmax[n0 + tid]; s_rs[tid] = vrs[n0 + tid]; }
    __syncthreads();

    int wid = tid >> 5, lane = tid & 31;
    int g = lane >> 2, tig = lane & 3;
    int wm = (wid & 3) * 32, wn = (wid >> 2) * 32;

    int am = tid >> 1, ak = (tid & 1) * 16;
    int bkk = tid >> 3, bjq = (tid & 7) * 8;   // yi=0
    int bj = tid >> 2, bkq = (tid & 3) * 8;    // yi=1

    float4 sA[4], sB[2];
    float c[2][4][4] = {};

    auto loadT = [&](int k0) {
#pragma unroll
        for (int q = 0; q < 4; q++) sA[q] = *(const float4*)&Zp[am * NPIX + k0 + ak + q * 4];
        if (yi == 0) {
#pragma unroll
            for (int q = 0; q < 2; q++)
                sB[q] = *(const float4*)&Ep[(k0 + bkk) * NPIX + n0 + bjq + q * 4];
        } else {
#pragma unroll
            for (int q = 0; q < 2; q++)
                sB[q] = *(const float4*)&Ep[(n0 + bj) * NPIX + k0 + bkq + q * 4];
        }
    };
    auto storeT = [&]() {
#pragma unroll
        for (int q = 0; q < 4; q++) {
            *(uint4*)&As[am][ak + q * 4] = make_uint4(
                f2t(sA[q].x), f2t(sA[q].y), f2t(sA[q].z), f2t(sA[q].w));
        }
        if (yi == 0) {
            uint32_t* brow = &Bs[bkk * 72 + bjq];
#pragma unroll
            for (int q = 0; q < 2; q++) {
                brow[q*4+0] = f2t(__expf(sB[q].x - s_max[bjq + q*4 + 0]));
                brow[q*4+1] = f2t(__expf(sB[q].y - s_max[bjq + q*4 + 1]));
                brow[q*4+2] = f2t(__expf(sB[q].z - s_max[bjq + q*4 + 2]));
                brow[q*4+3] = f2t(__expf(sB[q].w - s_max[bjq + q*4 + 3]));
            }
        } else {
            float mxj = s_max[bj];
            uint32_t* brow = &Bs[bj * 36 + bkq];
#pragma unroll
            for (int q = 0; q < 2; q++) {
                brow[q*4+0] = f2t(__expf(sB[q].x - mxj));
                brow[q*4+1] = f2t(__expf(sB[q].y - mxj));
                brow[q*4+2] = f2t(__expf(sB[q].z - mxj));
                brow[q*4+3] = f2t(__expf(sB[q].w - mxj));
            }
        }
    };

    loadT(0); storeT(); __syncthreads();
    for (int t = 0; t < 72; t++) {
        if (t < 71) loadT((t + 1) * 32);
#pragma unroll
        for (int kk = 0; kk < 32; kk += 8) {
            uint32_t a[2][4];
#pragma unroll
            for (int mi = 0; mi < 2; mi++) {
                int mr = wm + mi * 16;
                a[mi][0]=As[mr+g  ][kk+tig  ]; a[mi][1]=As[mr+g+8][kk+tig  ];
                a[mi][2]=As[mr+g  ][kk+tig+4]; a[mi][3]=As[mr+g+8][kk+tig+4];
            }
#pragma unroll
            for (int ni = 0; ni < 4; ni++) {
                uint32_t bb[2];
                if (yi == 0) {
                    bb[0] = Bs[(kk+tig  ) * 72 + wn + ni*8 + g];
                    bb[1] = Bs[(kk+tig+4) * 72 + wn + ni*8 + g];
                } else {
                    bb[0] = Bs[(wn + ni*8 + g) * 36 + kk + tig    ];
                    bb[1] = Bs[(wn + ni*8 + g) * 36 + kk + tig + 4];
                }
                mma8(c[0][ni], a[0], bb);
                mma8(c[1][ni], a[1], bb);
            }
        }
        __syncthreads();
        if (t < 71) storeT();
        __syncthreads();
    }

    float* Yp = g_Y[yi][b];
#pragma unroll
    for (int mi = 0; mi < 2; mi++) {
#pragma unroll
        for (int ni = 0; ni < 4; ni++) {
            int row = wm + mi * 16 + g;
            int col = wn + ni * 8 + tig * 2;
            float r0 = s_rs[col], r1 = s_rs[col + 1];
            *(float2*)&Yp[row * NPIX + n0 + col] =
                make_float2(c[mi][ni][0] * r0, c[mi][ni][1] * r1);
            *(float2*)&Yp[(row + 8) * NPIX + n0 + col] =
                make_float2(c[mi][ni][2] * r0, c[mi][ni][3] * r1);
        }
    }
}

// ======================================================================
// k_post_mma: out = W@Y + bias + residual. tf32, pipelined, 128x64.
// ======================================================================
__global__ void __launch_bounds__(256) k_post_mma(const float* __restrict__ x1,
                                                  const float* __restrict__ x2,
                                                  float* __restrict__ out)
{
    int i = blockIdx.z >> 2, b = blockIdx.z & 3;
    int m0 = blockIdx.y * 128, n0 = blockIdx.x * 64;
    const float* __restrict__ Asrc = g_Wpost[i];
    const float* __restrict__ Bsrc = g_Y[i][b];

    __shared__ uint32_t As[128][36];
    __shared__ uint32_t Bs[32][72];

    int tid = threadIdx.x;
    int wid = tid >> 5, lane = tid & 31;
    int g = lane >> 2, tig = lane & 3;
    int wm = (wid & 3) * 32, wn = (wid >> 2) * 32;

    int am = tid >> 1, ak = (tid & 1) * 16;
    int bkk = tid >> 3, bjq = (tid & 7) * 8;

    float4 sA[4], sB[2];
    float c[2][4][4] = {};

    auto loadT = [&](int k0) {
#pragma unroll
        for (int q = 0; q < 4; q++) sA[q] = *(const float4*)&Asrc[(m0 + am) * CI + k0 + ak + q * 4];
#pragma unroll
        for (int q = 0; q < 2; q++) sB[q] = *(const float4*)&Bsrc[(k0 + bkk) * NPIX + n0 + bjq + q * 4];
    };
    auto storeT = [&]() {
#pragma unroll
        for (int q = 0; q < 4; q++) {
            *(uint4*)&As[am][ak + q * 4] = make_uint4(
                f2t(sA[q].x), f2t(sA[q].y), f2t(sA[q].z), f2t(sA[q].w));
        }
#pragma unroll
        for (int q = 0; q < 2; q++) {
            *(uint4*)&Bs[bkk][bjq + q * 4] = make_uint4(
                f2t(sB[q].x), f2t(sB[q].y), f2t(sB[q].z), f2t(sB[q].w));
        }
    };

    loadT(0); storeT(); __syncthreads();
    for (int t = 0; t < 4; t++) {
        if (t < 3) loadT((t + 1) * 32);
#pragma unroll
        for (int kk = 0; kk < 32; kk += 8) {
            uint32_t a[2][4];
#pragma unroll
            for (int mi = 0; mi < 2; mi++) {
                int mr = wm + mi * 16;
                a[mi][0]=As[mr+g  ][kk+tig  ]; a[mi][1]=As[mr+g+8][kk+tig  ];
                a[mi][2]=As[mr+g  ][kk+tig+4]; a[mi][3]=As[mr+g+8][kk+tig+4];
            }
#pragma unroll
            for (int ni = 0; ni < 4; ni++) {
                uint32_t bb[2];
                bb[0]=Bs[kk+tig  ][wn+ni*8+g];
                bb[1]=Bs[kk+tig+4][wn+ni*8+g];
                mma8(c[0][ni], a[0], bb);
                mma8(c[1][ni], a[1], bb);
            }
        }
        __syncthreads();
        if (t < 3) storeT();
        __syncthreads();
    }

    const float* xs = (i ? x2 : x1) + b * CC * NPIX;
    float* op = out + (size_t)i * BATCH * CC * NPIX + (size_t)b * CC * NPIX;
#pragma unroll
    for (int mi = 0; mi < 2; mi++) {
#pragma unroll
        for (int ni = 0; ni < 4; ni++) {
            int row = m0 + wm + mi * 16 + g;
            int col = n0 + wn + ni * 8 + tig * 2;
            float b0 = g_bpost[i][row], b1 = g_bpost[i][row + 8];
            float2 r0 = *(const float2*)&xs[row * NPIX + col];
            float2 r1 = *(const float2*)&xs[(row + 8) * NPIX + col];
            *(float2*)&op[row * NPIX + col] =
                make_float2(c[mi][ni][0] + b0 + r0.x, c[mi][ni][1] + b0 + r0.y);
            *(float2*)&op[(row + 8) * NPIX + col] =
                make_float2(c[mi][ni][2] + b1 + r1.x, c[mi][ni][3] + b1 + r1.y);
        }
    }
}

// ---------------- launcher ----------------
extern "C" void kernel_launch(void* const* d_in, const int* in_sizes, int n_in,
                              void* d_out, int out_size)
{
    const float* x1      = (const float*)d_in[0];
    const float* x2      = (const float*)d_in[1];
    const float* bn_pre  = (const float*)d_in[2];
    const float* w_pre   = (const float*)d_in[3];
    const float* b_pre   = (const float*)d_in[4];
    const float* w_post  = (const float*)d_in[5];
    const float* b_post  = (const float*)d_in[6];
    const float* bn_post = (const float*)d_in[7];
    float* out = (float*)d_out;

    k_fold<<<2, 512>>>(bn_pre, w_pre, b_pre, w_post, b_post, bn_post);
    k_pre_bf16<<<dim3(36, 1, 16), 256>>>(x1, x2);
    k_etime_bf16<<<dim3(2, ETSPLIT, BATCH), 256>>>();
    k_etreduce<<<dim3(64, BATCH), 256>>>();
    k_softmax_time<<<BATCH, 128>>>();
    k_espace_bf16<<<dim3(36, 18, BATCH), 256>>>();
    k_zgemm_mma<<<dim3(36, 1, 8), 256>>>();
    k_colpart<<<dim3(9, NCHUNK, BATCH), 256>>>();
    k_colreduce<<<dim3(9, BATCH), 256>>>();
    k_rowstats<<<dim3(288, BATCH), 256>>>();
    k_ygemm_mma<<<dim3(36, 1, 8), 256>>>();
    k_post_mma<<<dim3(36, 2, 8), 256>>>(x1, x2, out);
}